// round 13
// baseline (speedup 1.0000x reference)
#include <cuda_runtime.h>
#include <cuda_bf16.h>
#include <cstdint>

#define N_NODES 100000
#define N_EDGES 600000
#define N_GRAPHS 64
#define BN_EPS 1e-5f
#define SCAN_BS 256
#define NB_SCAN ((N_NODES + SCAN_BS - 1) / SCAN_BS)   // 391
#define EB ((N_EDGES + 255) / 256)                     // 2344
#define WTOT 30720
#define WB ((WTOT + 255) / 256)                        // 120
#define HALF_NODES 50048                                // 391 * 128

// ================= helpers =================
__device__ __forceinline__ uint32_t smem_u32(const void* p) {
    uint32_t a;
    asm("{ .reg .u64 t; cvta.to.shared.u64 t, %1; cvt.u32.u64 %0, t; }" : "=r"(a) : "l"(p));
    return a;
}
__device__ __forceinline__ void sts32(uint32_t addr, uint32_t v) {
    asm volatile("st.shared.b32 [%0], %1;" :: "r"(addr), "r"(v));
}
__device__ __forceinline__ void ldsm4(uint32_t r[4], uint32_t a) {
    asm volatile("ldmatrix.sync.aligned.m8n8.x4.shared.b16 {%0,%1,%2,%3}, [%4];"
                 : "=r"(r[0]), "=r"(r[1]), "=r"(r[2]), "=r"(r[3]) : "r"(a));
}
__device__ __forceinline__ void ldsm2(uint32_t r[2], uint32_t a) {
    asm volatile("ldmatrix.sync.aligned.m8n8.x2.shared.b16 {%0,%1}, [%2];"
                 : "=r"(r[0]), "=r"(r[1]) : "r"(a));
}
__device__ __forceinline__ void mma_bf16(float c[4], const uint32_t a[4], const uint32_t b[2]) {
    asm volatile("mma.sync.aligned.m16n8k16.row.col.f32.bf16.bf16.f32 "
                 "{%0,%1,%2,%3}, {%4,%5,%6,%7}, {%8,%9}, {%0,%1,%2,%3};"
                 : "+f"(c[0]), "+f"(c[1]), "+f"(c[2]), "+f"(c[3])
                 : "r"(a[0]), "r"(a[1]), "r"(a[2]), "r"(a[3]), "r"(b[0]), "r"(b[1]));
}
__device__ __forceinline__ void split2(float a, float b, uint32_t& hi, uint32_t& lo) {
    __nv_bfloat16 ha = __float2bfloat16(a), hb = __float2bfloat16(b);
    __nv_bfloat16 la = __float2bfloat16(a - __bfloat162float(ha));
    __nv_bfloat16 lb = __float2bfloat16(b - __bfloat162float(hb));
    __nv_bfloat162 H; H.x = ha; H.y = hb;
    __nv_bfloat162 L; L.x = la; L.y = lb;
    hi = *(uint32_t*)&H; lo = *(uint32_t*)&L;
}

// ================= scratch =================
__device__ float g_ya[(size_t)N_NODES * 64];
__device__ float g_yb[(size_t)N_NODES * 64];
__device__ __nv_bfloat16 g_aghi[(size_t)N_NODES * 64];
__device__ __nv_bfloat16 g_aglo[(size_t)N_NODES * 64];
__device__ float g_f[(size_t)N_NODES * 96];
__device__ float g_sums[N_GRAPHS * 96];
__device__ int   g_cnts[N_GRAPHS];
__device__ int   g_batch32[N_NODES];
__device__ int   g_deg[N_NODES];
__device__ int   g_rowptr[N_NODES + 1];
__device__ int   g_cursor[N_NODES];
__device__ int   g_col[N_EDGES];
__device__ unsigned long long g_scanstate[NB_SCAN];
__device__ int   g_flags[2];
__device__ __nv_bfloat16 g_whi[WTOT];
__device__ __nv_bfloat16 g_wlo[WTOT];

// ================= graph-side prep =================
__global__ void prep_graph_kernel(const void* ei, const void* batch, int* flags,
                                  int* __restrict__ deg, float* __restrict__ sums,
                                  int* __restrict__ cnts,
                                  unsigned long long* __restrict__ sstate) {
    int b = blockIdx.x, t = threadIdx.x;
    if (b < NB_SCAN) {
        int i = b * 256 + t;
        if (i < N_NODES) deg[i] = 0;
        if (t == 0) sstate[b] = 0ULL;
    } else if (b == NB_SCAN || b == NB_SCAN + 1) {
        __shared__ int ok;
        if (t == 0) ok = 1;
        __syncthreads();
        int which = b - NB_SCAN;
        const void* p = (which == 0) ? ei : batch;
        long long n64_max = (which == 0) ? (long long)N_EDGES : (long long)N_NODES / 2;
        int maxval = (which == 0) ? N_NODES : N_GRAPHS;
        long long idx = (long long)t * (n64_max - 1) / 255;
        long long v = ((const long long*)p)[idx];
        if (v < 0 || v >= maxval) atomicAnd(&ok, 0);
        __syncthreads();
        if (t == 0) flags[which] = ok;
    } else {
        for (int i = t; i < N_GRAPHS * 96; i += 256) sums[i] = 0.f;
        if (t < N_GRAPHS) cnts[t] = 0;
    }
}

// ================= weight split (independent branch) =================
__global__ void wsplit_kernel(const float* w10, const float* w20, const float* w11,
                              const float* w21, const float* w12, const float* w22,
                              __nv_bfloat16* __restrict__ whi, __nv_bfloat16* __restrict__ wlo) {
    int i = blockIdx.x * blockDim.x + threadIdx.x;
    if (i >= WTOT) return;
    const float* src; int K, off;
    if      (i < 8192)  { src = w10; K = 128; off = 0; }
    else if (i < 12288) { src = w20; K = 64;  off = 8192; }
    else if (i < 16384) { src = w11; K = 64;  off = 12288; }
    else if (i < 20480) { src = w21; K = 64;  off = 16384; }
    else if (i < 24576) { src = w12; K = 64;  off = 20480; }
    else                { src = w22; K = 64;  off = 24576; }
    int N = (i < 24576) ? 64 : 96;
    int local = i - off;
    int n = local / K, k = local % K;
    float v = src[k * N + n];
    __nv_bfloat16 h = __float2bfloat16(v);
    whi[i] = h;
    wlo[i] = __float2bfloat16(v - __bfloat162float(h));
}

// ================= convert: deg histogram + batch -> int32 =================
__global__ void convert_all_kernel(const void* ei, const void* batch, const int* flags,
                                   int* __restrict__ deg, int* __restrict__ b32) {
    int b = blockIdx.x, t = threadIdx.x;
    if (b < EB) {
        int i = b * 256 + t;
        if (i >= N_EDGES) return;
        int d;
        if (flags[0]) d = (int)((const long long*)ei)[N_EDGES + i];
        else          d = ((const int*)ei)[N_EDGES + i];
        atomicAdd(&deg[d], 1);
    } else {
        int i = (b - EB) * 256 + t;
        if (i >= N_NODES) return;
        if (flags[1]) b32[i] = (int)((const long long*)batch)[i];
        else          b32[i] = ((const int*)batch)[i];
    }
}

// ================= single-pass exclusive scan (decoupled lookback) =================
__global__ void scan_onepass_kernel(const int* __restrict__ deg,
                                    int* __restrict__ rowptr, int* __restrict__ cursor,
                                    unsigned long long* __restrict__ sstate) {
    __shared__ int sm[SCAN_BS];
    __shared__ int s_off;
    int b = blockIdx.x, t = threadIdx.x;
    int i = b * SCAN_BS + t;
    int v = (i < N_NODES) ? deg[i] : 0;
    sm[t] = v;
    __syncthreads();
    for (int off = 1; off < SCAN_BS; off <<= 1) {
        int x = (t >= off) ? sm[t - off] : 0;
        __syncthreads();
        sm[t] += x;
        __syncthreads();
    }
    int total = sm[SCAN_BS - 1];
    if (t == 0) {
        if (b == 0) {
            atomicExch(&sstate[0], (2ULL << 32) | (unsigned)total);
            s_off = 0;
        } else {
            atomicExch(&sstate[b], (1ULL << 32) | (unsigned)total);
            int run = 0;
            int j = b - 1;
            while (true) {
                unsigned long long w = atomicAdd(&sstate[j], 0ULL);
                unsigned st = (unsigned)(w >> 32);
                if (st == 0) { __nanosleep(40); continue; }
                run += (int)(w & 0xffffffffULL);
                if (st == 2) break;
                j--;
            }
            atomicExch(&sstate[b], (2ULL << 32) | (unsigned)(run + total));
            s_off = run;
        }
    }
    __syncthreads();
    int off0 = s_off;
    if (i < N_NODES) {
        int r = off0 + sm[t] - v;
        rowptr[i] = r;
        cursor[i] = r;
    }
    if (i == N_NODES - 1) rowptr[N_NODES] = off0 + sm[t];
}

// ================= fill: CSR column array from raw ei =================
__global__ void fill_kernel(const void* ei, const int* flags,
                            int* __restrict__ cursor, int* __restrict__ col) {
    int e = blockIdx.x * blockDim.x + threadIdx.x;
    if (e >= N_EDGES) return;
    int s, d;
    if (flags[0]) {
        const long long* p = (const long long*)ei;
        s = (int)p[e]; d = (int)p[N_EDGES + e];
    } else {
        const int* p = (const int*)ei;
        s = p[e]; d = p[N_EDGES + e];
    }
    int pos = atomicAdd(&cursor[d], 1);
    col[pos] = s;
}

// ================= standalone GEMM layer0: Y = X @ W1 (K=128, N=64) =================
__global__ __launch_bounds__(128) void hgemm_l0(const float* __restrict__ X,
                                                const __nv_bfloat16* __restrict__ Whi,
                                                const __nv_bfloat16* __restrict__ Wlo,
                                                float* __restrict__ Y) {
    constexpr int K = 128, N = 64;
    constexpr int SP = K + 8, SPB = SP * 2, NT = N / 8;
    extern __shared__ char dsm[];
    uint32_t aHi = smem_u32(dsm);
    uint32_t aLo = aHi + 128 * SPB;
    uint32_t wHi = aLo + 128 * SPB;
    uint32_t wLo = wHi + N * SPB;

    const int tid = threadIdx.x, warp = tid >> 5, lane = tid & 31;
    const int base = blockIdx.x * 128;

    for (int i = tid; i < N * K / 2; i += 128) {
        int byte = i * 4;
        int row = byte / (K * 2), kb = byte - row * (K * 2);
        uint32_t off = (uint32_t)row * SPB + kb;
        sts32(wHi + off, ((const uint32_t*)Whi)[i]);
        sts32(wLo + off, ((const uint32_t*)Wlo)[i]);
    }
    constexpr int N4 = K / 4;
    for (int i = tid; i < 128 * N4; i += 128) {
        int row = i / N4, c4 = i - row * N4, col = c4 * 4;
        float4 v = make_float4(0.f, 0.f, 0.f, 0.f);
        if (base + row < N_NODES) v = ((const float4*)X)[(size_t)(base + row) * N4 + c4];
        uint32_t h01, l01, h23, l23;
        split2(v.x, v.y, h01, l01);
        split2(v.z, v.w, h23, l23);
        uint32_t off = (uint32_t)row * SPB + col * 2;
        sts32(aHi + off, h01); sts32(aHi + off + 4, h23);
        sts32(aLo + off, l01); sts32(aLo + off + 4, l23);
    }
    __syncthreads();

    float acc[2][NT][4];
#pragma unroll
    for (int t = 0; t < 2; t++)
#pragma unroll
        for (int n = 0; n < NT; n++)
#pragma unroll
            for (int j = 0; j < 4; j++) acc[t][n][j] = 0.f;

    const int arow = warp * 32 + (lane & 15);
    const int ahalf = lane >> 4;
    const int brow = lane & 7;
    const int bhalf = (lane >> 3) & 1;

#pragma unroll
    for (int s = 0; s < 3; s++) {
        uint32_t Ab = (s == 2) ? aLo : aHi;
        uint32_t Wb = (s == 1) ? wLo : wHi;
#pragma unroll
        for (int k16 = 0; k16 < K / 16; k16++) {
            uint32_t kbyte = (uint32_t)(k16 * 16) * 2;
            uint32_t af0[4], af1[4];
            ldsm4(af0, Ab + (uint32_t)arow * SPB + kbyte + ahalf * 16);
            ldsm4(af1, Ab + (uint32_t)(arow + 16) * SPB + kbyte + ahalf * 16);
#pragma unroll
            for (int n8 = 0; n8 < NT; n8++) {
                uint32_t bf[2];
                ldsm2(bf, Wb + (uint32_t)(n8 * 8 + brow) * SPB + kbyte + bhalf * 16);
                mma_bf16(acc[0][n8], af0, bf);
                mma_bf16(acc[1][n8], af1, bf);
            }
        }
    }
    const int r_in_warp = lane >> 2;
    const int cpair = (lane & 3) * 2;
#pragma unroll
    for (int t = 0; t < 2; t++) {
        int row0 = base + warp * 32 + t * 16 + r_in_warp;
        int row1 = row0 + 8;
#pragma unroll
        for (int n8 = 0; n8 < NT; n8++) {
            int col = n8 * 8 + cpair;
            if (row0 < N_NODES) *(float2*)(Y + (size_t)row0 * N + col) = make_float2(acc[t][n8][0], acc[t][n8][1]);
            if (row1 < N_NODES) *(float2*)(Y + (size_t)row1 * N + col) = make_float2(acc[t][n8][2], acc[t][n8][3]);
        }
    }
}

// ================= gather over node range [wbase, wend) =================
__global__ __launch_bounds__(256) void gather_kernel(const float* __restrict__ Y,
                                                     const int* __restrict__ rowptr,
                                                     const int* __restrict__ col,
                                                     const float* __restrict__ b1,
                                                     __nv_bfloat16* __restrict__ AGhi,
                                                     __nv_bfloat16* __restrict__ AGlo,
                                                     int wbase, int wend) {
    int w = wbase + ((blockIdx.x * blockDim.x + threadIdx.x) >> 5);
    int lane = threadIdx.x & 31;
    if (w >= wend) return;
    const float2* y2 = (const float2*)Y;
    float2 bias = ((const float2*)b1)[lane];
    int r0 = rowptr[w], r1 = rowptr[w + 1];
    float2 acc = y2[(size_t)w * 32 + lane];
    int e = r0;
    for (; e + 3 < r1; e += 4) {
        int s0 = col[e], s1 = col[e + 1], s2 = col[e + 2], s3 = col[e + 3];
        float2 a = y2[(size_t)s0 * 32 + lane];
        float2 b = y2[(size_t)s1 * 32 + lane];
        float2 c = y2[(size_t)s2 * 32 + lane];
        float2 d = y2[(size_t)s3 * 32 + lane];
        acc.x += (a.x + b.x) + (c.x + d.x);
        acc.y += (a.y + b.y) + (c.y + d.y);
    }
    if (e + 1 < r1) {
        int s0 = col[e], s1 = col[e + 1];
        float2 a = y2[(size_t)s0 * 32 + lane];
        float2 b = y2[(size_t)s1 * 32 + lane];
        acc.x += a.x + b.x;
        acc.y += a.y + b.y;
        e += 2;
    }
    if (e < r1) {
        int s = col[e];
        float2 a = y2[(size_t)s * 32 + lane];
        acc.x += a.x;
        acc.y += a.y;
    }
    acc.x = fmaxf(acc.x + bias.x, 0.f);
    acc.y = fmaxf(acc.y + bias.y, 0.f);
    uint32_t hi, lo;
    split2(acc.x, acc.y, hi, lo);
    ((uint32_t*)AGhi)[(size_t)w * 32 + lane] = hi;
    ((uint32_t*)AGlo)[(size_t)w * 32 + lane] = lo;
}

// ================= fused MLP over node range starting at node_base =================
template <int NOUT, bool CHAIN>
__global__ __launch_bounds__(128) void fused_mlp(const __nv_bfloat16* __restrict__ AGhi,
                                                 const __nv_bfloat16* __restrict__ AGlo,
                                                 const __nv_bfloat16* __restrict__ W2hi,
                                                 const __nv_bfloat16* __restrict__ W2lo,
                                                 const float* __restrict__ b2,
                                                 const float* __restrict__ bng,
                                                 const float* __restrict__ bnb,
                                                 const float* __restrict__ bnm,
                                                 const float* __restrict__ bnv,
                                                 const __nv_bfloat16* __restrict__ W1hi,
                                                 const __nv_bfloat16* __restrict__ W1lo,
                                                 float* __restrict__ OUT,
                                                 int node_base) {
    constexpr int K = 64;
    constexpr int SP = K + 8, SPB = SP * 2;
    constexpr int NT = NOUT / 8;
    extern __shared__ char dsm[];
    uint32_t aHi = smem_u32(dsm);
    uint32_t aLo = aHi + 128 * SPB;
    uint32_t wHi = aLo + 128 * SPB;
    uint32_t wLo = wHi + NOUT * SPB;
    __shared__ float sScale[NOUT];
    __shared__ float sShift[NOUT];

    const int tid = threadIdx.x, warp = tid >> 5, lane = tid & 31;
    const int base = node_base + blockIdx.x * 128;

    if (tid < NOUT) {
        float s = bng[tid] * rsqrtf(bnv[tid] + BN_EPS);
        sScale[tid] = s;
        sShift[tid] = (b2[tid] - bnm[tid]) * s + bnb[tid];
    }
    for (int i = tid; i < NOUT * K / 2; i += 128) {
        int byte = i * 4;
        int row = byte >> 7, kb = byte & 127;
        uint32_t off = (uint32_t)row * SPB + kb;
        sts32(wHi + off, ((const uint32_t*)W2hi)[i]);
        sts32(wLo + off, ((const uint32_t*)W2lo)[i]);
    }
    for (int i = tid; i < 128 * 32; i += 128) {
        int row = i >> 5, w = i & 31;
        uint32_t h = 0, l = 0;
        if (base + row < N_NODES) {
            h = ((const uint32_t*)AGhi)[(size_t)(base + row) * 32 + w];
            l = ((const uint32_t*)AGlo)[(size_t)(base + row) * 32 + w];
        }
        uint32_t off = (uint32_t)row * SPB + w * 4;
        sts32(aHi + off, h);
        sts32(aLo + off, l);
    }
    __syncthreads();

    float acc[2][NT][4];
#pragma unroll
    for (int t = 0; t < 2; t++)
#pragma unroll
        for (int n = 0; n < NT; n++)
#pragma unroll
            for (int j = 0; j < 4; j++) acc[t][n][j] = 0.f;

    const int arow = warp * 32 + (lane & 15);
    const int ahalf = lane >> 4;
    const int brow = lane & 7;
    const int bhalf = (lane >> 3) & 1;

#pragma unroll
    for (int s = 0; s < 3; s++) {
        uint32_t Ab = (s == 2) ? aLo : aHi;
        uint32_t Wb = (s == 1) ? wLo : wHi;
#pragma unroll
        for (int k16 = 0; k16 < 4; k16++) {
            uint32_t kbyte = (uint32_t)(k16 * 32);
            uint32_t af0[4], af1[4];
            ldsm4(af0, Ab + (uint32_t)arow * SPB + kbyte + ahalf * 16);
            ldsm4(af1, Ab + (uint32_t)(arow + 16) * SPB + kbyte + ahalf * 16);
#pragma unroll
            for (int n8 = 0; n8 < NT; n8++) {
                uint32_t bf[2];
                ldsm2(bf, Wb + (uint32_t)(n8 * 8 + brow) * SPB + kbyte + bhalf * 16);
                mma_bf16(acc[0][n8], af0, bf);
                mma_bf16(acc[1][n8], af1, bf);
            }
        }
    }

    const int r_in_warp = lane >> 2;
    const int cpair = (lane & 3) * 2;
#pragma unroll
    for (int t = 0; t < 2; t++) {
#pragma unroll
        for (int n8 = 0; n8 < NT; n8++) {
            int c = n8 * 8 + cpair;
            acc[t][n8][0] = fmaxf(acc[t][n8][0] * sScale[c] + sShift[c], 0.f);
            acc[t][n8][1] = fmaxf(acc[t][n8][1] * sScale[c + 1] + sShift[c + 1], 0.f);
            acc[t][n8][2] = fmaxf(acc[t][n8][2] * sScale[c] + sShift[c], 0.f);
            acc[t][n8][3] = fmaxf(acc[t][n8][3] * sScale[c + 1] + sShift[c + 1], 0.f);
        }
    }

    if (!CHAIN) {
#pragma unroll
        for (int t = 0; t < 2; t++) {
            int row0 = base + warp * 32 + t * 16 + r_in_warp;
            int row1 = row0 + 8;
#pragma unroll
            for (int n8 = 0; n8 < NT; n8++) {
                int c = n8 * 8 + cpair;
                if (row0 < N_NODES) *(float2*)(OUT + (size_t)row0 * NOUT + c) = make_float2(acc[t][n8][0], acc[t][n8][1]);
                if (row1 < N_NODES) *(float2*)(OUT + (size_t)row1 * NOUT + c) = make_float2(acc[t][n8][2], acc[t][n8][3]);
            }
        }
        return;
    }

    __syncthreads();
#pragma unroll
    for (int t = 0; t < 2; t++) {
        int rl0 = warp * 32 + t * 16 + r_in_warp;
        int rl1 = rl0 + 8;
#pragma unroll
        for (int n8 = 0; n8 < NT; n8++) {
            int cb = (n8 * 8 + cpair) * 2;
            uint32_t h, l;
            split2(acc[t][n8][0], acc[t][n8][1], h, l);
            sts32(aHi + (uint32_t)rl0 * SPB + cb, h);
            sts32(aLo + (uint32_t)rl0 * SPB + cb, l);
            split2(acc[t][n8][2], acc[t][n8][3], h, l);
            sts32(aHi + (uint32_t)rl1 * SPB + cb, h);
            sts32(aLo + (uint32_t)rl1 * SPB + cb, l);
        }
    }
    for (int i = tid; i < 64 * K / 2; i += 128) {
        int byte = i * 4;
        int row = byte >> 7, kb = byte & 127;
        uint32_t off = (uint32_t)row * SPB + kb;
        sts32(wHi + off, ((const uint32_t*)W1hi)[i]);
        sts32(wLo + off, ((const uint32_t*)W1lo)[i]);
    }
    __syncthreads();

    float acc2[2][8][4];
#pragma unroll
    for (int t = 0; t < 2; t++)
#pragma unroll
        for (int n = 0; n < 8; n++)
#pragma unroll
            for (int j = 0; j < 4; j++) acc2[t][n][j] = 0.f;

#pragma unroll
    for (int s = 0; s < 3; s++) {
        uint32_t Ab = (s == 2) ? aLo : aHi;
        uint32_t Wb = (s == 1) ? wLo : wHi;
#pragma unroll
        for (int k16 = 0; k16 < 4; k16++) {
            uint32_t kbyte = (uint32_t)(k16 * 32);
            uint32_t af0[4], af1[4];
            ldsm4(af0, Ab + (uint32_t)arow * SPB + kbyte + ahalf * 16);
            ldsm4(af1, Ab + (uint32_t)(arow + 16) * SPB + kbyte + ahalf * 16);
#pragma unroll
            for (int n8 = 0; n8 < 8; n8++) {
                uint32_t bf[2];
                ldsm2(bf, Wb + (uint32_t)(n8 * 8 + brow) * SPB + kbyte + bhalf * 16);
                mma_bf16(acc2[0][n8], af0, bf);
                mma_bf16(acc2[1][n8], af1, bf);
            }
        }
    }
#pragma unroll
    for (int t = 0; t < 2; t++) {
        int row0 = base + warp * 32 + t * 16 + r_in_warp;
        int row1 = row0 + 8;
#pragma unroll
        for (int n8 = 0; n8 < 8; n8++) {
            int c = n8 * 8 + cpair;
            if (row0 < N_NODES) *(float2*)(OUT + (size_t)row0 * 64 + c) = make_float2(acc2[t][n8][0], acc2[t][n8][1]);
            if (row1 < N_NODES) *(float2*)(OUT + (size_t)row1 * 64 + c) = make_float2(acc2[t][n8][2], acc2[t][n8][3]);
        }
    }
}

// ================= pool =================
#define PB_NODES 64
__global__ void pool_kernel(const float* __restrict__ F, const int* __restrict__ batch,
                            float* __restrict__ sums, int* __restrict__ cnts) {
    __shared__ int sb[PB_NODES];
    const int start = blockIdx.x * PB_NODES;
    const int nn = min(PB_NODES, N_NODES - start);
    const int tid = threadIdx.x;   // 96
    if (tid < nn) sb[tid] = batch[start + tid];
    __syncthreads();
    if (tid == 0) {
        int cur = sb[0], c = 0;
        for (int n = 0; n < nn; n++) {
            int g = sb[n];
            if (g != cur) { atomicAdd(&cnts[cur], c); cur = g; c = 0; }
            c++;
        }
        atomicAdd(&cnts[cur], c);
    }
    int cur = sb[0];
    float acc = 0.f;
    for (int n = 0; n < nn; n++) {
        int g = sb[n];
        float v = F[(size_t)(start + n) * 96 + tid];
        if (g != cur) { atomicAdd(&sums[cur * 96 + tid], acc); acc = 0.f; cur = g; }
        acc += v;
    }
    atomicAdd(&sums[cur * 96 + tid], acc);
}
__global__ void finalize_kernel(const float* __restrict__ sums, const int* __restrict__ cnts,
                                float* __restrict__ out) {
    int i = blockIdx.x * blockDim.x + threadIdx.x;
    if (i >= N_GRAPHS * 96) return;
    float c = fmaxf((float)cnts[i / 96], 1.f);
    out[i] = sums[i] / c;
}

// ================= launch =================
extern "C" void kernel_launch(void* const* d_in, const int* in_sizes, int n_in,
                              void* d_out, int out_size) {
    const float* x     = (const float*)d_in[0];
    const void*  ei    = d_in[1];
    const void*  batch = d_in[2];
    const float* P[24];
    for (int i = 0; i < 24; i++) P[i] = (const float*)d_in[3 + i];

    float *ya, *yb, *f, *sums;
    __nv_bfloat16 *aghi, *aglo, *whi, *wlo;
    int *cnts, *b32, *flags;
    int *deg, *rowptr, *cursor, *colv;
    unsigned long long* sstate;
    cudaGetSymbolAddress((void**)&ya,     g_ya);
    cudaGetSymbolAddress((void**)&yb,     g_yb);
    cudaGetSymbolAddress((void**)&aghi,   g_aghi);
    cudaGetSymbolAddress((void**)&aglo,   g_aglo);
    cudaGetSymbolAddress((void**)&f,      g_f);
    cudaGetSymbolAddress((void**)&sums,   g_sums);
    cudaGetSymbolAddress((void**)&cnts,   g_cnts);
    cudaGetSymbolAddress((void**)&b32,    g_batch32);
    cudaGetSymbolAddress((void**)&flags,  g_flags);
    cudaGetSymbolAddress((void**)&deg,    g_deg);
    cudaGetSymbolAddress((void**)&rowptr, g_rowptr);
    cudaGetSymbolAddress((void**)&cursor, g_cursor);
    cudaGetSymbolAddress((void**)&colv,   g_col);
    cudaGetSymbolAddress((void**)&sstate, g_scanstate);
    cudaGetSymbolAddress((void**)&whi,    g_whi);
    cudaGetSymbolAddress((void**)&wlo,    g_wlo);

    const int SM_L0  = (256 + 128) * (136 * 2);   // 104448
    const int SM_F64 = (256 + 128) * (72 * 2);    // 55296
    const int SM_F96 = (256 + 192) * (72 * 2);    // 64512
    cudaFuncSetAttribute((const void*)hgemm_l0, cudaFuncAttributeMaxDynamicSharedMemorySize, SM_L0);
    cudaFuncSetAttribute((const void*)fused_mlp<64, true>,  cudaFuncAttributeMaxDynamicSharedMemorySize, SM_F64);
    cudaFuncSetAttribute((const void*)fused_mlp<96, false>, cudaFuncAttributeMaxDynamicSharedMemorySize, SM_F96);

    const int NB = (N_NODES + 127) / 128;          // 782
    const int NBA = HALF_NODES / 128;              // 391
    const int NBB = NB - NBA;                      // 391
    const int GA = (HALF_NODES * 32 + 255) / 256;              // 6256
    const int GBn = ((N_NODES - HALF_NODES) * 32 + 255) / 256; // 6244

    cudaStream_t s2;
    cudaStreamCreateWithFlags(&s2, cudaStreamNonBlocking);
    cudaEvent_t evFork, evJoin, evGA[3], evFA[3];
    cudaEventCreateWithFlags(&evFork, cudaEventDisableTiming);
    cudaEventCreateWithFlags(&evJoin, cudaEventDisableTiming);
    for (int l = 0; l < 3; l++) {
        cudaEventCreateWithFlags(&evGA[l], cudaEventDisableTiming);
        cudaEventCreateWithFlags(&evFA[l], cudaEventDisableTiming);
    }

    cudaEventRecord(evFork, 0);
    cudaStreamWaitEvent(s2, evFork, 0);

    // --- branch B (s2): weights + layer-0 GEMM -> ya ---
    const int O_W10 = 0, O_W20 = 8192, O_W11 = 12288, O_W21 = 16384, O_W12 = 20480, O_W22 = 24576;
    wsplit_kernel<<<WB, 256, 0, s2>>>(P[0], P[2], P[8], P[10], P[16], P[18], whi, wlo);
    hgemm_l0<<<NB, 128, SM_L0, s2>>>(x, whi + O_W10, wlo + O_W10, ya);
    cudaEventRecord(evJoin, s2);

    // --- branch A (stream 0): CSR build ---
    prep_graph_kernel<<<NB_SCAN + 3, 256>>>(ei, batch, flags, deg, sums, cnts, sstate);
    convert_all_kernel<<<EB + NB_SCAN, 256>>>(ei, batch, flags, deg, b32);
    scan_onepass_kernel<<<NB_SCAN, SCAN_BS>>>(deg, rowptr, cursor, sstate);
    fill_kernel<<<EB, 256>>>(ei, flags, cursor, colv);

    cudaStreamWaitEvent(0, evJoin, 0);

    // pipelined layer: gatherA(s0) -> fusedA(s2) || gatherB+fusedB(s0); join before next layer
    const float* YIN[3] = { ya, yb, ya };
    float*       YOUT2[3] = { yb, ya, f };
    const float* B1[3] = { P[1], P[9], P[17] };
    const int OW2[3] = { O_W20, O_W21, O_W22 };
    const int OW1n[3] = { O_W11, O_W12, 0 };
    const float* BP[3][5] = { {P[3], P[4], P[5], P[6], P[7]},
                              {P[11], P[12], P[13], P[14], P[15]},
                              {P[19], P[20], P[21], P[22], P[23]} };

    for (int l = 0; l < 3; l++) {
        gather_kernel<<<GA, 256>>>(YIN[l], rowptr, colv, B1[l], aghi, aglo, 0, HALF_NODES);
        cudaEventRecord(evGA[l], 0);
        cudaStreamWaitEvent(s2, evGA[l], 0);
        if (l < 2) {
            fused_mlp<64, true><<<NBA, 128, SM_F64, s2>>>(aghi, aglo, whi + OW2[l], wlo + OW2[l],
                BP[l][0], BP[l][1], BP[l][2], BP[l][3], BP[l][4],
                whi + OW1n[l], wlo + OW1n[l], YOUT2[l], 0);
        } else {
            fused_mlp<96, false><<<NBA, 128, SM_F96, s2>>>(aghi, aglo, whi + OW2[l], wlo + OW2[l],
                BP[l][0], BP[l][1], BP[l][2], BP[l][3], BP[l][4],
                nullptr, nullptr, YOUT2[l], 0);
        }
        cudaEventRecord(evFA[l], s2);

        gather_kernel<<<GBn, 256>>>(YIN[l], rowptr, colv, B1[l], aghi, aglo, HALF_NODES, N_NODES);
        if (l < 2) {
            fused_mlp<64, true><<<NBB, 128, SM_F64>>>(aghi, aglo, whi + OW2[l], wlo + OW2[l],
                BP[l][0], BP[l][1], BP[l][2], BP[l][3], BP[l][4],
                whi + OW1n[l], wlo + OW1n[l], YOUT2[l], HALF_NODES);
        } else {
            fused_mlp<96, false><<<NBB, 128, SM_F96>>>(aghi, aglo, whi + OW2[l], wlo + OW2[l],
                BP[l][0], BP[l][1], BP[l][2], BP[l][3], BP[l][4],
                nullptr, nullptr, YOUT2[l], HALF_NODES);
        }
        cudaStreamWaitEvent(0, evFA[l], 0);
    }

    pool_kernel<<<(N_NODES + PB_NODES - 1) / PB_NODES, 96>>>(f, b32, sums, cnts);
    finalize_kernel<<<(N_GRAPHS * 96 + 255) / 256, 256>>>(sums, cnts, (float*)d_out);

    cudaEventDestroy(evFork);
    cudaEventDestroy(evJoin);
    for (int l = 0; l < 3; l++) { cudaEventDestroy(evGA[l]); cudaEventDestroy(evFA[l]); }
    cudaStreamDestroy(s2);
}

// round 14
// speedup vs baseline: 1.0946x; 1.0946x over previous
#include <cuda_runtime.h>
#include <cuda_bf16.h>
#include <cstdint>

#define N_NODES 100000
#define N_EDGES 600000
#define N_GRAPHS 64
#define BN_EPS 1e-5f
#define SCAN_BS 256
#define NB_SCAN ((N_NODES + SCAN_BS - 1) / SCAN_BS)   // 391
#define EB ((N_EDGES + 255) / 256)                     // 2344
#define NBB ((N_NODES + 255) / 256)                    // 391
#define WTOT 30720
#define WB ((WTOT + 255) / 256)                        // 120

// ================= helpers =================
__device__ __forceinline__ uint32_t smem_u32(const void* p) {
    uint32_t a;
    asm("{ .reg .u64 t; cvta.to.shared.u64 t, %1; cvt.u32.u64 %0, t; }" : "=r"(a) : "l"(p));
    return a;
}
__device__ __forceinline__ void sts32(uint32_t addr, uint32_t v) {
    asm volatile("st.shared.b32 [%0], %1;" :: "r"(addr), "r"(v));
}
__device__ __forceinline__ void ldsm4(uint32_t r[4], uint32_t a) {
    asm volatile("ldmatrix.sync.aligned.m8n8.x4.shared.b16 {%0,%1,%2,%3}, [%4];"
                 : "=r"(r[0]), "=r"(r[1]), "=r"(r[2]), "=r"(r[3]) : "r"(a));
}
__device__ __forceinline__ void ldsm2(uint32_t r[2], uint32_t a) {
    asm volatile("ldmatrix.sync.aligned.m8n8.x2.shared.b16 {%0,%1}, [%2];"
                 : "=r"(r[0]), "=r"(r[1]) : "r"(a));
}
__device__ __forceinline__ void mma_bf16(float c[4], const uint32_t a[4], const uint32_t b[2]) {
    asm volatile("mma.sync.aligned.m16n8k16.row.col.f32.bf16.bf16.f32 "
                 "{%0,%1,%2,%3}, {%4,%5,%6,%7}, {%8,%9}, {%0,%1,%2,%3};"
                 : "+f"(c[0]), "+f"(c[1]), "+f"(c[2]), "+f"(c[3])
                 : "r"(a[0]), "r"(a[1]), "r"(a[2]), "r"(a[3]), "r"(b[0]), "r"(b[1]));
}
__device__ __forceinline__ void split2(float a, float b, uint32_t& hi, uint32_t& lo) {
    __nv_bfloat16 ha = __float2bfloat16(a), hb = __float2bfloat16(b);
    __nv_bfloat16 la = __float2bfloat16(a - __bfloat162float(ha));
    __nv_bfloat16 lb = __float2bfloat16(b - __bfloat162float(hb));
    __nv_bfloat162 H; H.x = ha; H.y = hb;
    __nv_bfloat162 L; L.x = la; L.y = lb;
    hi = *(uint32_t*)&H; lo = *(uint32_t*)&L;
}

// ================= scratch =================
__device__ float g_y[(size_t)N_NODES * 64];
__device__ __nv_bfloat16 g_aghi[(size_t)N_NODES * 64];
__device__ __nv_bfloat16 g_aglo[(size_t)N_NODES * 64];
__device__ float g_f[(size_t)N_NODES * 96];
__device__ float g_sums[N_GRAPHS * 96];
__device__ int   g_cnts[N_GRAPHS];
__device__ int   g_batch32[N_NODES];
__device__ int   g_deg[N_NODES];
__device__ int   g_rowptr[N_NODES + 1];
__device__ int   g_cursor[N_NODES];
__device__ int   g_col[N_EDGES];
__device__ unsigned long long g_scanstate[NB_SCAN];
__device__ int   g_flags[2];
__device__ __nv_bfloat16 g_whi[WTOT];
__device__ __nv_bfloat16 g_wlo[WTOT];

// ================= branch-A prep: detect dtypes + zero deg/scanstate =================
__global__ void prep_graph_kernel(const void* ei, const void* batch, int* flags,
                                  int* __restrict__ deg,
                                  unsigned long long* __restrict__ sstate) {
    int b = blockIdx.x, t = threadIdx.x;
    if (b < NB_SCAN) {
        int i = b * 256 + t;
        if (i < N_NODES) deg[i] = 0;
        if (t == 0) sstate[b] = 0ULL;
    } else {
        __shared__ int ok;
        if (t == 0) ok = 1;
        __syncthreads();
        int which = b - NB_SCAN;
        const void* p = (which == 0) ? ei : batch;
        long long n64_max = (which == 0) ? (long long)N_EDGES : (long long)N_NODES / 2;
        int maxval = (which == 0) ? N_NODES : N_GRAPHS;
        long long idx = (long long)t * (n64_max - 1) / 255;
        long long v = ((const long long*)p)[idx];
        if (v < 0 || v >= maxval) atomicAnd(&ok, 0);
        __syncthreads();
        if (t == 0) flags[which] = ok;
    }
}

// ================= branch-B side work: batch convert + pool zeroing =================
__global__ void side_kernel(const void* batch, const int* flags,
                            int* __restrict__ b32,
                            float* __restrict__ sums, int* __restrict__ cnts) {
    int b = blockIdx.x, t = threadIdx.x;
    if (b < NBB) {
        int i = b * 256 + t;
        if (i >= N_NODES) return;
        if (flags[1]) b32[i] = (int)((const long long*)batch)[i];
        else          b32[i] = ((const int*)batch)[i];
    } else {
        for (int i = t; i < N_GRAPHS * 96; i += 256) sums[i] = 0.f;
        if (t < N_GRAPHS) cnts[t] = 0;
    }
}

// ================= weight split =================
__global__ void wsplit_kernel(const float* w10, const float* w20, const float* w11,
                              const float* w21, const float* w12, const float* w22,
                              __nv_bfloat16* __restrict__ whi, __nv_bfloat16* __restrict__ wlo) {
    int i = blockIdx.x * blockDim.x + threadIdx.x;
    if (i >= WTOT) return;
    const float* src; int K, off;
    if      (i < 8192)  { src = w10; K = 128; off = 0; }
    else if (i < 12288) { src = w20; K = 64;  off = 8192; }
    else if (i < 16384) { src = w11; K = 64;  off = 12288; }
    else if (i < 20480) { src = w21; K = 64;  off = 16384; }
    else if (i < 24576) { src = w12; K = 64;  off = 20480; }
    else                { src = w22; K = 64;  off = 24576; }
    int N = (i < 24576) ? 64 : 96;
    int local = i - off;
    int n = local / K, k = local % K;
    float v = src[k * N + n];
    __nv_bfloat16 h = __float2bfloat16(v);
    whi[i] = h;
    wlo[i] = __float2bfloat16(v - __bfloat162float(h));
}

// ================= deg histogram from raw ei =================
__global__ void hist_kernel(const void* ei, const int* flags, int* __restrict__ deg) {
    int i = blockIdx.x * blockDim.x + threadIdx.x;
    if (i >= N_EDGES) return;
    int d;
    if (flags[0]) d = (int)((const long long*)ei)[N_EDGES + i];
    else          d = ((const int*)ei)[N_EDGES + i];
    atomicAdd(&deg[d], 1);
}

// ================= single-pass exclusive scan (decoupled lookback) =================
__global__ void scan_onepass_kernel(const int* __restrict__ deg,
                                    int* __restrict__ rowptr, int* __restrict__ cursor,
                                    unsigned long long* __restrict__ sstate) {
    __shared__ int sm[SCAN_BS];
    __shared__ int s_off;
    int b = blockIdx.x, t = threadIdx.x;
    int i = b * SCAN_BS + t;
    int v = (i < N_NODES) ? deg[i] : 0;
    sm[t] = v;
    __syncthreads();
    for (int off = 1; off < SCAN_BS; off <<= 1) {
        int x = (t >= off) ? sm[t - off] : 0;
        __syncthreads();
        sm[t] += x;
        __syncthreads();
    }
    int total = sm[SCAN_BS - 1];
    if (t == 0) {
        if (b == 0) {
            atomicExch(&sstate[0], (2ULL << 32) | (unsigned)total);
            s_off = 0;
        } else {
            atomicExch(&sstate[b], (1ULL << 32) | (unsigned)total);
            int run = 0;
            int j = b - 1;
            while (true) {
                unsigned long long w = atomicAdd(&sstate[j], 0ULL);
                unsigned st = (unsigned)(w >> 32);
                if (st == 0) { __nanosleep(40); continue; }
                run += (int)(w & 0xffffffffULL);
                if (st == 2) break;
                j--;
            }
            atomicExch(&sstate[b], (2ULL << 32) | (unsigned)(run + total));
            s_off = run;
        }
    }
    __syncthreads();
    int off0 = s_off;
    if (i < N_NODES) {
        int r = off0 + sm[t] - v;
        rowptr[i] = r;
        cursor[i] = r;
    }
    if (i == N_NODES - 1) rowptr[N_NODES] = off0 + sm[t];
}

// ================= fill: CSR column array from raw ei =================
__global__ void fill_kernel(const void* ei, const int* flags,
                            int* __restrict__ cursor, int* __restrict__ col) {
    int e = blockIdx.x * blockDim.x + threadIdx.x;
    if (e >= N_EDGES) return;
    int s, d;
    if (flags[0]) {
        const long long* p = (const long long*)ei;
        s = (int)p[e]; d = (int)p[N_EDGES + e];
    } else {
        const int* p = (const int*)ei;
        s = p[e]; d = p[N_EDGES + e];
    }
    int pos = atomicAdd(&cursor[d], 1);
    col[pos] = s;
}

// ================= standalone GEMM layer0: Y = X @ W1 (K=128, N=64) =================
__global__ __launch_bounds__(128) void hgemm_l0(const float* __restrict__ X,
                                                const __nv_bfloat16* __restrict__ Whi,
                                                const __nv_bfloat16* __restrict__ Wlo,
                                                float* __restrict__ Y) {
    constexpr int K = 128, N = 64;
    constexpr int SP = K + 8, SPB = SP * 2, NT = N / 8;
    extern __shared__ char dsm[];
    uint32_t aHi = smem_u32(dsm);
    uint32_t aLo = aHi + 128 * SPB;
    uint32_t wHi = aLo + 128 * SPB;
    uint32_t wLo = wHi + N * SPB;

    const int tid = threadIdx.x, warp = tid >> 5, lane = tid & 31;
    const int base = blockIdx.x * 128;

    for (int i = tid; i < N * K / 2; i += 128) {
        int byte = i * 4;
        int row = byte / (K * 2), kb = byte - row * (K * 2);
        uint32_t off = (uint32_t)row * SPB + kb;
        sts32(wHi + off, ((const uint32_t*)Whi)[i]);
        sts32(wLo + off, ((const uint32_t*)Wlo)[i]);
    }
    constexpr int N4 = K / 4;
    for (int i = tid; i < 128 * N4; i += 128) {
        int row = i / N4, c4 = i - row * N4, col = c4 * 4;
        float4 v = make_float4(0.f, 0.f, 0.f, 0.f);
        if (base + row < N_NODES) v = ((const float4*)X)[(size_t)(base + row) * N4 + c4];
        uint32_t h01, l01, h23, l23;
        split2(v.x, v.y, h01, l01);
        split2(v.z, v.w, h23, l23);
        uint32_t off = (uint32_t)row * SPB + col * 2;
        sts32(aHi + off, h01); sts32(aHi + off + 4, h23);
        sts32(aLo + off, l01); sts32(aLo + off + 4, l23);
    }
    __syncthreads();

    float acc[2][NT][4];
#pragma unroll
    for (int t = 0; t < 2; t++)
#pragma unroll
        for (int n = 0; n < NT; n++)
#pragma unroll
            for (int j = 0; j < 4; j++) acc[t][n][j] = 0.f;

    const int arow = warp * 32 + (lane & 15);
    const int ahalf = lane >> 4;
    const int brow = lane & 7;
    const int bhalf = (lane >> 3) & 1;

#pragma unroll
    for (int s = 0; s < 3; s++) {
        uint32_t Ab = (s == 2) ? aLo : aHi;
        uint32_t Wb = (s == 1) ? wLo : wHi;
#pragma unroll
        for (int k16 = 0; k16 < K / 16; k16++) {
            uint32_t kbyte = (uint32_t)(k16 * 16) * 2;
            uint32_t af0[4], af1[4];
            ldsm4(af0, Ab + (uint32_t)arow * SPB + kbyte + ahalf * 16);
            ldsm4(af1, Ab + (uint32_t)(arow + 16) * SPB + kbyte + ahalf * 16);
#pragma unroll
            for (int n8 = 0; n8 < NT; n8++) {
                uint32_t bf[2];
                ldsm2(bf, Wb + (uint32_t)(n8 * 8 + brow) * SPB + kbyte + bhalf * 16);
                mma_bf16(acc[0][n8], af0, bf);
                mma_bf16(acc[1][n8], af1, bf);
            }
        }
    }
    const int r_in_warp = lane >> 2;
    const int cpair = (lane & 3) * 2;
#pragma unroll
    for (int t = 0; t < 2; t++) {
        int row0 = base + warp * 32 + t * 16 + r_in_warp;
        int row1 = row0 + 8;
#pragma unroll
        for (int n8 = 0; n8 < NT; n8++) {
            int col = n8 * 8 + cpair;
            if (row0 < N_NODES) *(float2*)(Y + (size_t)row0 * N + col) = make_float2(acc[t][n8][0], acc[t][n8][1]);
            if (row1 < N_NODES) *(float2*)(Y + (size_t)row1 * N + col) = make_float2(acc[t][n8][2], acc[t][n8][3]);
        }
    }
}

// ================= gather: AG = split(ReLU(gathersum + b1)) as bf16 hi/lo =================
__global__ __launch_bounds__(256) void gather_kernel(const float* __restrict__ Y,
                                                     const int* __restrict__ rowptr,
                                                     const int* __restrict__ col,
                                                     const float* __restrict__ b1,
                                                     __nv_bfloat16* __restrict__ AGhi,
                                                     __nv_bfloat16* __restrict__ AGlo) {
    int w = (blockIdx.x * blockDim.x + threadIdx.x) >> 5;
    int lane = threadIdx.x & 31;
    if (w >= N_NODES) return;
    const float2* y2 = (const float2*)Y;
    float2 bias = ((const float2*)b1)[lane];
    int r0 = rowptr[w], r1 = rowptr[w + 1];
    float2 acc = y2[(size_t)w * 32 + lane];
    int e = r0;
    for (; e + 3 < r1; e += 4) {
        int s0 = col[e], s1 = col[e + 1], s2 = col[e + 2], s3 = col[e + 3];
        float2 a = y2[(size_t)s0 * 32 + lane];
        float2 b = y2[(size_t)s1 * 32 + lane];
        float2 c = y2[(size_t)s2 * 32 + lane];
        float2 d = y2[(size_t)s3 * 32 + lane];
        acc.x += (a.x + b.x) + (c.x + d.x);
        acc.y += (a.y + b.y) + (c.y + d.y);
    }
    if (e + 1 < r1) {
        int s0 = col[e], s1 = col[e + 1];
        float2 a = y2[(size_t)s0 * 32 + lane];
        float2 b = y2[(size_t)s1 * 32 + lane];
        acc.x += a.x + b.x;
        acc.y += a.y + b.y;
        e += 2;
    }
    if (e < r1) {
        int s = col[e];
        float2 a = y2[(size_t)s * 32 + lane];
        acc.x += a.x;
        acc.y += a.y;
    }
    acc.x = fmaxf(acc.x + bias.x, 0.f);
    acc.y = fmaxf(acc.y + bias.y, 0.f);
    uint32_t hi, lo;
    split2(acc.x, acc.y, hi, lo);
    ((uint32_t*)AGhi)[(size_t)w * 32 + lane] = hi;
    ((uint32_t*)AGlo)[(size_t)w * 32 + lane] = lo;
}

// ================= fused MLP: AG(bf16) @ W2 -> BN+ReLU -> [@W1next -> Y | out] =================
template <int NOUT, bool CHAIN>
__global__ __launch_bounds__(128) void fused_mlp(const __nv_bfloat16* __restrict__ AGhi,
                                                 const __nv_bfloat16* __restrict__ AGlo,
                                                 const __nv_bfloat16* __restrict__ W2hi,
                                                 const __nv_bfloat16* __restrict__ W2lo,
                                                 const float* __restrict__ b2,
                                                 const float* __restrict__ bng,
                                                 const float* __restrict__ bnb,
                                                 const float* __restrict__ bnm,
                                                 const float* __restrict__ bnv,
                                                 const __nv_bfloat16* __restrict__ W1hi,
                                                 const __nv_bfloat16* __restrict__ W1lo,
                                                 float* __restrict__ OUT) {
    constexpr int K = 64;
    constexpr int SP = K + 8, SPB = SP * 2;
    constexpr int NT = NOUT / 8;
    extern __shared__ char dsm[];
    uint32_t aHi = smem_u32(dsm);
    uint32_t aLo = aHi + 128 * SPB;
    uint32_t wHi = aLo + 128 * SPB;
    uint32_t wLo = wHi + NOUT * SPB;
    __shared__ float sScale[NOUT];
    __shared__ float sShift[NOUT];

    const int tid = threadIdx.x, warp = tid >> 5, lane = tid & 31;
    const int base = blockIdx.x * 128;

    if (tid < NOUT) {
        float s = bng[tid] * rsqrtf(bnv[tid] + BN_EPS);
        sScale[tid] = s;
        sShift[tid] = (b2[tid] - bnm[tid]) * s + bnb[tid];
    }
    for (int i = tid; i < NOUT * K / 2; i += 128) {
        int byte = i * 4;
        int row = byte >> 7, kb = byte & 127;
        uint32_t off = (uint32_t)row * SPB + kb;
        sts32(wHi + off, ((const uint32_t*)W2hi)[i]);
        sts32(wLo + off, ((const uint32_t*)W2lo)[i]);
    }
    for (int i = tid; i < 128 * 32; i += 128) {
        int row = i >> 5, w = i & 31;
        uint32_t h = 0, l = 0;
        if (base + row < N_NODES) {
            h = ((const uint32_t*)AGhi)[(size_t)(base + row) * 32 + w];
            l = ((const uint32_t*)AGlo)[(size_t)(base + row) * 32 + w];
        }
        uint32_t off = (uint32_t)row * SPB + w * 4;
        sts32(aHi + off, h);
        sts32(aLo + off, l);
    }
    __syncthreads();

    float acc[2][NT][4];
#pragma unroll
    for (int t = 0; t < 2; t++)
#pragma unroll
        for (int n = 0; n < NT; n++)
#pragma unroll
            for (int j = 0; j < 4; j++) acc[t][n][j] = 0.f;

    const int arow = warp * 32 + (lane & 15);
    const int ahalf = lane >> 4;
    const int brow = lane & 7;
    const int bhalf = (lane >> 3) & 1;

#pragma unroll
    for (int s = 0; s < 3; s++) {
        uint32_t Ab = (s == 2) ? aLo : aHi;
        uint32_t Wb = (s == 1) ? wLo : wHi;
#pragma unroll
        for (int k16 = 0; k16 < 4; k16++) {
            uint32_t kbyte = (uint32_t)(k16 * 32);
            uint32_t af0[4], af1[4];
            ldsm4(af0, Ab + (uint32_t)arow * SPB + kbyte + ahalf * 16);
            ldsm4(af1, Ab + (uint32_t)(arow + 16) * SPB + kbyte + ahalf * 16);
#pragma unroll
            for (int n8 = 0; n8 < NT; n8++) {
                uint32_t bf[2];
                ldsm2(bf, Wb + (uint32_t)(n8 * 8 + brow) * SPB + kbyte + bhalf * 16);
                mma_bf16(acc[0][n8], af0, bf);
                mma_bf16(acc[1][n8], af1, bf);
            }
        }
    }

    const int r_in_warp = lane >> 2;
    const int cpair = (lane & 3) * 2;
#pragma unroll
    for (int t = 0; t < 2; t++) {
#pragma unroll
        for (int n8 = 0; n8 < NT; n8++) {
            int c = n8 * 8 + cpair;
            acc[t][n8][0] = fmaxf(acc[t][n8][0] * sScale[c] + sShift[c], 0.f);
            acc[t][n8][1] = fmaxf(acc[t][n8][1] * sScale[c + 1] + sShift[c + 1], 0.f);
            acc[t][n8][2] = fmaxf(acc[t][n8][2] * sScale[c] + sShift[c], 0.f);
            acc[t][n8][3] = fmaxf(acc[t][n8][3] * sScale[c + 1] + sShift[c + 1], 0.f);
        }
    }

    if (!CHAIN) {
#pragma unroll
        for (int t = 0; t < 2; t++) {
            int row0 = base + warp * 32 + t * 16 + r_in_warp;
            int row1 = row0 + 8;
#pragma unroll
            for (int n8 = 0; n8 < NT; n8++) {
                int c = n8 * 8 + cpair;
                if (row0 < N_NODES) *(float2*)(OUT + (size_t)row0 * NOUT + c) = make_float2(acc[t][n8][0], acc[t][n8][1]);
                if (row1 < N_NODES) *(float2*)(OUT + (size_t)row1 * NOUT + c) = make_float2(acc[t][n8][2], acc[t][n8][3]);
            }
        }
        return;
    }

    __syncthreads();
#pragma unroll
    for (int t = 0; t < 2; t++) {
        int rl0 = warp * 32 + t * 16 + r_in_warp;
        int rl1 = rl0 + 8;
#pragma unroll
        for (int n8 = 0; n8 < NT; n8++) {
            int cb = (n8 * 8 + cpair) * 2;
            uint32_t h, l;
            split2(acc[t][n8][0], acc[t][n8][1], h, l);
            sts32(aHi + (uint32_t)rl0 * SPB + cb, h);
            sts32(aLo + (uint32_t)rl0 * SPB + cb, l);
            split2(acc[t][n8][2], acc[t][n8][3], h, l);
            sts32(aHi + (uint32_t)rl1 * SPB + cb, h);
            sts32(aLo + (uint32_t)rl1 * SPB + cb, l);
        }
    }
    for (int i = tid; i < 64 * K / 2; i += 128) {
        int byte = i * 4;
        int row = byte >> 7, kb = byte & 127;
        uint32_t off = (uint32_t)row * SPB + kb;
        sts32(wHi + off, ((const uint32_t*)W1hi)[i]);
        sts32(wLo + off, ((const uint32_t*)W1lo)[i]);
    }
    __syncthreads();

    float acc2[2][8][4];
#pragma unroll
    for (int t = 0; t < 2; t++)
#pragma unroll
        for (int n = 0; n < 8; n++)
#pragma unroll
            for (int j = 0; j < 4; j++) acc2[t][n][j] = 0.f;

#pragma unroll
    for (int s = 0; s < 3; s++) {
        uint32_t Ab = (s == 2) ? aLo : aHi;
        uint32_t Wb = (s == 1) ? wLo : wHi;
#pragma unroll
        for (int k16 = 0; k16 < 4; k16++) {
            uint32_t kbyte = (uint32_t)(k16 * 32);
            uint32_t af0[4], af1[4];
            ldsm4(af0, Ab + (uint32_t)arow * SPB + kbyte + ahalf * 16);
            ldsm4(af1, Ab + (uint32_t)(arow + 16) * SPB + kbyte + ahalf * 16);
#pragma unroll
            for (int n8 = 0; n8 < 8; n8++) {
                uint32_t bf[2];
                ldsm2(bf, Wb + (uint32_t)(n8 * 8 + brow) * SPB + kbyte + bhalf * 16);
                mma_bf16(acc2[0][n8], af0, bf);
                mma_bf16(acc2[1][n8], af1, bf);
            }
        }
    }
#pragma unroll
    for (int t = 0; t < 2; t++) {
        int row0 = base + warp * 32 + t * 16 + r_in_warp;
        int row1 = row0 + 8;
#pragma unroll
        for (int n8 = 0; n8 < 8; n8++) {
            int c = n8 * 8 + cpair;
            if (row0 < N_NODES) *(float2*)(OUT + (size_t)row0 * 64 + c) = make_float2(acc2[t][n8][0], acc2[t][n8][1]);
            if (row1 < N_NODES) *(float2*)(OUT + (size_t)row1 * 64 + c) = make_float2(acc2[t][n8][2], acc2[t][n8][3]);
        }
    }
}

// ================= pool =================
#define PB_NODES 64
__global__ void pool_kernel(const float* __restrict__ F, const int* __restrict__ batch,
                            float* __restrict__ sums, int* __restrict__ cnts) {
    __shared__ int sb[PB_NODES];
    const int start = blockIdx.x * PB_NODES;
    const int nn = min(PB_NODES, N_NODES - start);
    const int tid = threadIdx.x;   // 96
    if (tid < nn) sb[tid] = batch[start + tid];
    __syncthreads();
    if (tid == 0) {
        int cur = sb[0], c = 0;
        for (int n = 0; n < nn; n++) {
            int g = sb[n];
            if (g != cur) { atomicAdd(&cnts[cur], c); cur = g; c = 0; }
            c++;
        }
        atomicAdd(&cnts[cur], c);
    }
    int cur = sb[0];
    float acc = 0.f;
    for (int n = 0; n < nn; n++) {
        int g = sb[n];
        float v = F[(size_t)(start + n) * 96 + tid];
        if (g != cur) { atomicAdd(&sums[cur * 96 + tid], acc); acc = 0.f; cur = g; }
        acc += v;
    }
    atomicAdd(&sums[cur * 96 + tid], acc);
}
__global__ void finalize_kernel(const float* __restrict__ sums, const int* __restrict__ cnts,
                                float* __restrict__ out) {
    int i = blockIdx.x * blockDim.x + threadIdx.x;
    if (i >= N_GRAPHS * 96) return;
    float c = fmaxf((float)cnts[i / 96], 1.f);
    out[i] = sums[i] / c;
}

// ================= launch =================
extern "C" void kernel_launch(void* const* d_in, const int* in_sizes, int n_in,
                              void* d_out, int out_size) {
    const float* x     = (const float*)d_in[0];
    const void*  ei    = d_in[1];
    const void*  batch = d_in[2];
    const float* P[24];
    for (int i = 0; i < 24; i++) P[i] = (const float*)d_in[3 + i];

    float *y, *f, *sums;
    __nv_bfloat16 *aghi, *aglo, *whi, *wlo;
    int *cnts, *b32, *flags;
    int *deg, *rowptr, *cursor, *colv;
    unsigned long long* sstate;
    cudaGetSymbolAddress((void**)&y,      g_y);
    cudaGetSymbolAddress((void**)&aghi,   g_aghi);
    cudaGetSymbolAddress((void**)&aglo,   g_aglo);
    cudaGetSymbolAddress((void**)&f,      g_f);
    cudaGetSymbolAddress((void**)&sums,   g_sums);
    cudaGetSymbolAddress((void**)&cnts,   g_cnts);
    cudaGetSymbolAddress((void**)&b32,    g_batch32);
    cudaGetSymbolAddress((void**)&flags,  g_flags);
    cudaGetSymbolAddress((void**)&deg,    g_deg);
    cudaGetSymbolAddress((void**)&rowptr, g_rowptr);
    cudaGetSymbolAddress((void**)&cursor, g_cursor);
    cudaGetSymbolAddress((void**)&colv,   g_col);
    cudaGetSymbolAddress((void**)&sstate, g_scanstate);
    cudaGetSymbolAddress((void**)&whi,    g_whi);
    cudaGetSymbolAddress((void**)&wlo,    g_wlo);

    const int SM_L0  = (256 + 128) * (136 * 2);   // 104448
    const int SM_F64 = (256 + 128) * (72 * 2);    // 55296
    const int SM_F96 = (256 + 192) * (72 * 2);    // 64512
    cudaFuncSetAttribute((const void*)hgemm_l0, cudaFuncAttributeMaxDynamicSharedMemorySize, SM_L0);
    cudaFuncSetAttribute((const void*)fused_mlp<64, true>,  cudaFuncAttributeMaxDynamicSharedMemorySize, SM_F64);
    cudaFuncSetAttribute((const void*)fused_mlp<96, false>, cudaFuncAttributeMaxDynamicSharedMemorySize, SM_F96);

    const int NB = (N_NODES + 127) / 128;          // 782
    const int GB = (N_NODES * 32 + 255) / 256;     // 12500

    cudaStream_t s2;
    cudaStreamCreateWithFlags(&s2, cudaStreamNonBlocking);
    cudaEvent_t evFork, evJoin, evFlags;
    cudaEventCreateWithFlags(&evFork, cudaEventDisableTiming);
    cudaEventCreateWithFlags(&evJoin, cudaEventDisableTiming);
    cudaEventCreateWithFlags(&evFlags, cudaEventDisableTiming);

    cudaEventRecord(evFork, 0);
    cudaStreamWaitEvent(s2, evFork, 0);

    // --- branch A (stream 0): CSR build (critical path) ---
    prep_graph_kernel<<<NB_SCAN + 2, 256>>>(ei, batch, flags, deg, sstate);
    cudaEventRecord(evFlags, 0);
    hist_kernel<<<EB, 256>>>(ei, flags, deg);
    scan_onepass_kernel<<<NB_SCAN, SCAN_BS>>>(deg, rowptr, cursor, sstate);
    fill_kernel<<<EB, 256>>>(ei, flags, cursor, colv);

    // --- branch B (s2): weights + layer-0 GEMM + batch convert + pool zero ---
    const int O_W10 = 0, O_W20 = 8192, O_W11 = 12288, O_W21 = 16384, O_W12 = 20480, O_W22 = 24576;
    wsplit_kernel<<<WB, 256, 0, s2>>>(P[0], P[2], P[8], P[10], P[16], P[18], whi, wlo);
    hgemm_l0<<<NB, 128, SM_L0, s2>>>(x, whi + O_W10, wlo + O_W10, y);
    cudaStreamWaitEvent(s2, evFlags, 0);   // side_kernel reads flags[1]
    side_kernel<<<NBB + 1, 256, 0, s2>>>(batch, flags, b32, sums, cnts);
    cudaEventRecord(evJoin, s2);

    // join: gather needs y (B) + rowptr/col (A)
    cudaStreamWaitEvent(0, evJoin, 0);

    gather_kernel<<<GB, 256>>>(y, rowptr, colv, P[1], aghi, aglo);
    fused_mlp<64, true><<<NB, 128, SM_F64>>>(aghi, aglo, whi + O_W20, wlo + O_W20,
                                             P[3], P[4], P[5], P[6], P[7],
                                             whi + O_W11, wlo + O_W11, y);
    gather_kernel<<<GB, 256>>>(y, rowptr, colv, P[9], aghi, aglo);
    fused_mlp<64, true><<<NB, 128, SM_F64>>>(aghi, aglo, whi + O_W21, wlo + O_W21,
                                             P[11], P[12], P[13], P[14], P[15],
                                             whi + O_W12, wlo + O_W12, y);
    gather_kernel<<<GB, 256>>>(y, rowptr, colv, P[17], aghi, aglo);
    fused_mlp<96, false><<<NB, 128, SM_F96>>>(aghi, aglo, whi + O_W22, wlo + O_W22,
                                              P[19], P[20], P[21], P[22], P[23],
                                              nullptr, nullptr, f);

    pool_kernel<<<(N_NODES + PB_NODES - 1) / PB_NODES, 96>>>(f, b32, sums, cnts);
    finalize_kernel<<<(N_GRAPHS * 96 + 255) / 256, 256>>>(sums, cnts, (float*)d_out);

    cudaEventDestroy(evFork);
    cudaEventDestroy(evJoin);
    cudaEventDestroy(evFlags);
    cudaStreamDestroy(s2);
}

// round 15
// speedup vs baseline: 1.1319x; 1.0341x over previous
#include <cuda_runtime.h>
#include <cuda_bf16.h>
#include <cstdint>

#define N_NODES 100000
#define N_EDGES 600000
#define N_GRAPHS 64
#define BN_EPS 1e-5f
#define SCAN_BS 256
#define NB_SCAN ((N_NODES + SCAN_BS - 1) / SCAN_BS)   // 391
#define EB ((N_EDGES + 255) / 256)                     // 2344
#define NBB ((N_NODES + 255) / 256)                    // 391
#define WTOT 30720
#define WB ((WTOT + 255) / 256)                        // 120

// ================= helpers =================
__device__ __forceinline__ uint32_t smem_u32(const void* p) {
    uint32_t a;
    asm("{ .reg .u64 t; cvta.to.shared.u64 t, %1; cvt.u32.u64 %0, t; }" : "=r"(a) : "l"(p));
    return a;
}
__device__ __forceinline__ void sts32(uint32_t addr, uint32_t v) {
    asm volatile("st.shared.b32 [%0], %1;" :: "r"(addr), "r"(v));
}
__device__ __forceinline__ void ldsm4(uint32_t r[4], uint32_t a) {
    asm volatile("ldmatrix.sync.aligned.m8n8.x4.shared.b16 {%0,%1,%2,%3}, [%4];"
                 : "=r"(r[0]), "=r"(r[1]), "=r"(r[2]), "=r"(r[3]) : "r"(a));
}
__device__ __forceinline__ void ldsm2(uint32_t r[2], uint32_t a) {
    asm volatile("ldmatrix.sync.aligned.m8n8.x2.shared.b16 {%0,%1}, [%2];"
                 : "=r"(r[0]), "=r"(r[1]) : "r"(a));
}
__device__ __forceinline__ void mma_bf16(float c[4], const uint32_t a[4], const uint32_t b[2]) {
    asm volatile("mma.sync.aligned.m16n8k16.row.col.f32.bf16.bf16.f32 "
                 "{%0,%1,%2,%3}, {%4,%5,%6,%7}, {%8,%9}, {%0,%1,%2,%3};"
                 : "+f"(c[0]), "+f"(c[1]), "+f"(c[2]), "+f"(c[3])
                 : "r"(a[0]), "r"(a[1]), "r"(a[2]), "r"(a[3]), "r"(b[0]), "r"(b[1]));
}
__device__ __forceinline__ void split2(float a, float b, uint32_t& hi, uint32_t& lo) {
    __nv_bfloat16 ha = __float2bfloat16(a), hb = __float2bfloat16(b);
    __nv_bfloat16 la = __float2bfloat16(a - __bfloat162float(ha));
    __nv_bfloat16 lb = __float2bfloat16(b - __bfloat162float(hb));
    __nv_bfloat162 H; H.x = ha; H.y = hb;
    __nv_bfloat162 L; L.x = la; L.y = lb;
    hi = *(uint32_t*)&H; lo = *(uint32_t*)&L;
}

// ================= scratch =================
__device__ float g_y[(size_t)N_NODES * 64];
__device__ __nv_bfloat16 g_aghi[(size_t)N_NODES * 64];
__device__ __nv_bfloat16 g_aglo[(size_t)N_NODES * 64];
__device__ float g_f[(size_t)N_NODES * 96];
__device__ float g_sums[N_GRAPHS * 96];
__device__ int   g_cnts[N_GRAPHS];
__device__ int   g_batch32[N_NODES];
__device__ int   g_deg[N_NODES];
__device__ int   g_rowptr[N_NODES + 1];
__device__ int   g_cursor[N_NODES];
__device__ int   g_col[N_EDGES];
__device__ unsigned long long g_scanstate[NB_SCAN];
__device__ int   g_flags[2];
__device__ __nv_bfloat16 g_whi[WTOT];
__device__ __nv_bfloat16 g_wlo[WTOT];

// ================= branch-A prep: detect dtypes + zero deg/scanstate =================
__global__ void prep_graph_kernel(const void* ei, const void* batch, int* flags,
                                  int* __restrict__ deg,
                                  unsigned long long* __restrict__ sstate) {
    int b = blockIdx.x, t = threadIdx.x;
    if (b < NB_SCAN) {
        int i = b * 256 + t;
        if (i < N_NODES) deg[i] = 0;
        if (t == 0) sstate[b] = 0ULL;
    } else {
        __shared__ int ok;
        if (t == 0) ok = 1;
        __syncthreads();
        int which = b - NB_SCAN;
        const void* p = (which == 0) ? ei : batch;
        long long n64_max = (which == 0) ? (long long)N_EDGES : (long long)N_NODES / 2;
        int maxval = (which == 0) ? N_NODES : N_GRAPHS;
        long long idx = (long long)t * (n64_max - 1) / 255;
        long long v = ((const long long*)p)[idx];
        if (v < 0 || v >= maxval) atomicAnd(&ok, 0);
        __syncthreads();
        if (t == 0) flags[which] = ok;
    }
}

// ================= branch-B side work: batch convert + pool zeroing =================
__global__ void side_kernel(const void* batch, const int* flags,
                            int* __restrict__ b32,
                            float* __restrict__ sums, int* __restrict__ cnts) {
    int b = blockIdx.x, t = threadIdx.x;
    if (b < NBB) {
        int i = b * 256 + t;
        if (i >= N_NODES) return;
        if (flags[1]) b32[i] = (int)((const long long*)batch)[i];
        else          b32[i] = ((const int*)batch)[i];
    } else {
        for (int i = t; i < N_GRAPHS * 96; i += 256) sums[i] = 0.f;
        if (t < N_GRAPHS) cnts[t] = 0;
    }
}

// ================= weight split =================
__global__ void wsplit_kernel(const float* w10, const float* w20, const float* w11,
                              const float* w21, const float* w12, const float* w22,
                              __nv_bfloat16* __restrict__ whi, __nv_bfloat16* __restrict__ wlo) {
    int i = blockIdx.x * blockDim.x + threadIdx.x;
    if (i >= WTOT) return;
    const float* src; int K, off;
    if      (i < 8192)  { src = w10; K = 128; off = 0; }
    else if (i < 12288) { src = w20; K = 64;  off = 8192; }
    else if (i < 16384) { src = w11; K = 64;  off = 12288; }
    else if (i < 20480) { src = w21; K = 64;  off = 16384; }
    else if (i < 24576) { src = w12; K = 64;  off = 20480; }
    else                { src = w22; K = 64;  off = 24576; }
    int N = (i < 24576) ? 64 : 96;
    int local = i - off;
    int n = local / K, k = local % K;
    float v = src[k * N + n];
    __nv_bfloat16 h = __float2bfloat16(v);
    whi[i] = h;
    wlo[i] = __float2bfloat16(v - __bfloat162float(h));
}

// ================= deg histogram from raw ei =================
__global__ void hist_kernel(const void* ei, const int* flags, int* __restrict__ deg) {
    int i = blockIdx.x * blockDim.x + threadIdx.x;
    if (i >= N_EDGES) return;
    int d;
    if (flags[0]) d = (int)((const long long*)ei)[N_EDGES + i];
    else          d = ((const int*)ei)[N_EDGES + i];
    atomicAdd(&deg[d], 1);
}

// ================= single-pass exclusive scan (decoupled lookback) =================
__global__ void scan_onepass_kernel(const int* __restrict__ deg,
                                    int* __restrict__ rowptr, int* __restrict__ cursor,
                                    unsigned long long* __restrict__ sstate) {
    __shared__ int sm[SCAN_BS];
    __shared__ int s_off;
    int b = blockIdx.x, t = threadIdx.x;
    int i = b * SCAN_BS + t;
    int v = (i < N_NODES) ? deg[i] : 0;
    sm[t] = v;
    __syncthreads();
    for (int off = 1; off < SCAN_BS; off <<= 1) {
        int x = (t >= off) ? sm[t - off] : 0;
        __syncthreads();
        sm[t] += x;
        __syncthreads();
    }
    int total = sm[SCAN_BS - 1];
    if (t == 0) {
        if (b == 0) {
            atomicExch(&sstate[0], (2ULL << 32) | (unsigned)total);
            s_off = 0;
        } else {
            atomicExch(&sstate[b], (1ULL << 32) | (unsigned)total);
            int run = 0;
            int j = b - 1;
            while (true) {
                unsigned long long w = atomicAdd(&sstate[j], 0ULL);
                unsigned st = (unsigned)(w >> 32);
                if (st == 0) { __nanosleep(40); continue; }
                run += (int)(w & 0xffffffffULL);
                if (st == 2) break;
                j--;
            }
            atomicExch(&sstate[b], (2ULL << 32) | (unsigned)(run + total));
            s_off = run;
        }
    }
    __syncthreads();
    int off0 = s_off;
    if (i < N_NODES) {
        int r = off0 + sm[t] - v;
        rowptr[i] = r;
        cursor[i] = r;
    }
    if (i == N_NODES - 1) rowptr[N_NODES] = off0 + sm[t];
}

// ================= fill: CSR column array from raw ei =================
__global__ void fill_kernel(const void* ei, const int* flags,
                            int* __restrict__ cursor, int* __restrict__ col) {
    int e = blockIdx.x * blockDim.x + threadIdx.x;
    if (e >= N_EDGES) return;
    int s, d;
    if (flags[0]) {
        const long long* p = (const long long*)ei;
        s = (int)p[e]; d = (int)p[N_EDGES + e];
    } else {
        const int* p = (const int*)ei;
        s = p[e]; d = p[N_EDGES + e];
    }
    int pos = atomicAdd(&cursor[d], 1);
    col[pos] = s;
}

// ================= standalone GEMM layer0: Y = X @ W1 (K=128, N=64) =================
__global__ __launch_bounds__(128) void hgemm_l0(const float* __restrict__ X,
                                                const __nv_bfloat16* __restrict__ Whi,
                                                const __nv_bfloat16* __restrict__ Wlo,
                                                float* __restrict__ Y) {
    constexpr int K = 128, N = 64;
    constexpr int SP = K + 8, SPB = SP * 2, NT = N / 8;
    extern __shared__ char dsm[];
    uint32_t aHi = smem_u32(dsm);
    uint32_t aLo = aHi + 128 * SPB;
    uint32_t wHi = aLo + 128 * SPB;
    uint32_t wLo = wHi + N * SPB;

    const int tid = threadIdx.x, warp = tid >> 5, lane = tid & 31;
    const int base = blockIdx.x * 128;

    for (int i = tid; i < N * K / 2; i += 128) {
        int byte = i * 4;
        int row = byte / (K * 2), kb = byte - row * (K * 2);
        uint32_t off = (uint32_t)row * SPB + kb;
        sts32(wHi + off, ((const uint32_t*)Whi)[i]);
        sts32(wLo + off, ((const uint32_t*)Wlo)[i]);
    }
    constexpr int N4 = K / 4;
    for (int i = tid; i < 128 * N4; i += 128) {
        int row = i / N4, c4 = i - row * N4, col = c4 * 4;
        float4 v = make_float4(0.f, 0.f, 0.f, 0.f);
        if (base + row < N_NODES) v = ((const float4*)X)[(size_t)(base + row) * N4 + c4];
        uint32_t h01, l01, h23, l23;
        split2(v.x, v.y, h01, l01);
        split2(v.z, v.w, h23, l23);
        uint32_t off = (uint32_t)row * SPB + col * 2;
        sts32(aHi + off, h01); sts32(aHi + off + 4, h23);
        sts32(aLo + off, l01); sts32(aLo + off + 4, l23);
    }
    __syncthreads();

    float acc[2][NT][4];
#pragma unroll
    for (int t = 0; t < 2; t++)
#pragma unroll
        for (int n = 0; n < NT; n++)
#pragma unroll
            for (int j = 0; j < 4; j++) acc[t][n][j] = 0.f;

    const int arow = warp * 32 + (lane & 15);
    const int ahalf = lane >> 4;
    const int brow = lane & 7;
    const int bhalf = (lane >> 3) & 1;

#pragma unroll
    for (int s = 0; s < 3; s++) {
        uint32_t Ab = (s == 2) ? aLo : aHi;
        uint32_t Wb = (s == 1) ? wLo : wHi;
#pragma unroll
        for (int k16 = 0; k16 < K / 16; k16++) {
            uint32_t kbyte = (uint32_t)(k16 * 16) * 2;
            uint32_t af0[4], af1[4];
            ldsm4(af0, Ab + (uint32_t)arow * SPB + kbyte + ahalf * 16);
            ldsm4(af1, Ab + (uint32_t)(arow + 16) * SPB + kbyte + ahalf * 16);
#pragma unroll
            for (int n8 = 0; n8 < NT; n8++) {
                uint32_t bf[2];
                ldsm2(bf, Wb + (uint32_t)(n8 * 8 + brow) * SPB + kbyte + bhalf * 16);
                mma_bf16(acc[0][n8], af0, bf);
                mma_bf16(acc[1][n8], af1, bf);
            }
        }
    }
    const int r_in_warp = lane >> 2;
    const int cpair = (lane & 3) * 2;
#pragma unroll
    for (int t = 0; t < 2; t++) {
        int row0 = base + warp * 32 + t * 16 + r_in_warp;
        int row1 = row0 + 8;
#pragma unroll
        for (int n8 = 0; n8 < NT; n8++) {
            int col = n8 * 8 + cpair;
            if (row0 < N_NODES) *(float2*)(Y + (size_t)row0 * N + col) = make_float2(acc[t][n8][0], acc[t][n8][1]);
            if (row1 < N_NODES) *(float2*)(Y + (size_t)row1 * N + col) = make_float2(acc[t][n8][2], acc[t][n8][3]);
        }
    }
}

// ================= gather: 2 nodes/warp, float4 lanes, AG = split(ReLU(sum + b1)) =================
__global__ __launch_bounds__(256) void gather_kernel(const float* __restrict__ Y,
                                                     const int* __restrict__ rowptr,
                                                     const int* __restrict__ col,
                                                     const float* __restrict__ b1,
                                                     __nv_bfloat16* __restrict__ AGhi,
                                                     __nv_bfloat16* __restrict__ AGlo) {
    int w = (blockIdx.x * blockDim.x + threadIdx.x) >> 4;   // node id (16-lane half)
    int lane = threadIdx.x & 15;                            // float4 column
    if (w >= N_NODES) return;
    const float4* y4 = (const float4*)Y;
    float4 bias = ((const float4*)b1)[lane];
    int r0 = rowptr[w], r1 = rowptr[w + 1];
    float4 acc = y4[(size_t)w * 16 + lane];
    int e = r0;
    for (; e + 3 < r1; e += 4) {
        int s0 = col[e], s1 = col[e + 1], s2 = col[e + 2], s3 = col[e + 3];
        float4 a = y4[(size_t)s0 * 16 + lane];
        float4 b = y4[(size_t)s1 * 16 + lane];
        float4 c = y4[(size_t)s2 * 16 + lane];
        float4 d = y4[(size_t)s3 * 16 + lane];
        acc.x += (a.x + b.x) + (c.x + d.x);
        acc.y += (a.y + b.y) + (c.y + d.y);
        acc.z += (a.z + b.z) + (c.z + d.z);
        acc.w += (a.w + b.w) + (c.w + d.w);
    }
    if (e + 1 < r1) {
        int s0 = col[e], s1 = col[e + 1];
        float4 a = y4[(size_t)s0 * 16 + lane];
        float4 b = y4[(size_t)s1 * 16 + lane];
        acc.x += a.x + b.x;
        acc.y += a.y + b.y;
        acc.z += a.z + b.z;
        acc.w += a.w + b.w;
        e += 2;
    }
    if (e < r1) {
        int s = col[e];
        float4 a = y4[(size_t)s * 16 + lane];
        acc.x += a.x; acc.y += a.y; acc.z += a.z; acc.w += a.w;
    }
    acc.x = fmaxf(acc.x + bias.x, 0.f);
    acc.y = fmaxf(acc.y + bias.y, 0.f);
    acc.z = fmaxf(acc.z + bias.z, 0.f);
    acc.w = fmaxf(acc.w + bias.w, 0.f);
    uint32_t h01, l01, h23, l23;
    split2(acc.x, acc.y, h01, l01);
    split2(acc.z, acc.w, h23, l23);
    *(uint2*)((uint32_t*)AGhi + (size_t)w * 32 + lane * 2) = make_uint2(h01, h23);
    *(uint2*)((uint32_t*)AGlo + (size_t)w * 32 + lane * 2) = make_uint2(l01, l23);
}

// ================= fused MLP: AG(bf16) @ W2 -> BN+ReLU -> [@W1next -> Y | out] =================
template <int NOUT, bool CHAIN>
__global__ __launch_bounds__(128) void fused_mlp(const __nv_bfloat16* __restrict__ AGhi,
                                                 const __nv_bfloat16* __restrict__ AGlo,
                                                 const __nv_bfloat16* __restrict__ W2hi,
                                                 const __nv_bfloat16* __restrict__ W2lo,
                                                 const float* __restrict__ b2,
                                                 const float* __restrict__ bng,
                                                 const float* __restrict__ bnb,
                                                 const float* __restrict__ bnm,
                                                 const float* __restrict__ bnv,
                                                 const __nv_bfloat16* __restrict__ W1hi,
                                                 const __nv_bfloat16* __restrict__ W1lo,
                                                 float* __restrict__ OUT) {
    constexpr int K = 64;
    constexpr int SP = K + 8, SPB = SP * 2;
    constexpr int NT = NOUT / 8;
    extern __shared__ char dsm[];
    uint32_t aHi = smem_u32(dsm);
    uint32_t aLo = aHi + 128 * SPB;
    uint32_t wHi = aLo + 128 * SPB;
    uint32_t wLo = wHi + NOUT * SPB;
    __shared__ float sScale[NOUT];
    __shared__ float sShift[NOUT];

    const int tid = threadIdx.x, warp = tid >> 5, lane = tid & 31;
    const int base = blockIdx.x * 128;

    if (tid < NOUT) {
        float s = bng[tid] * rsqrtf(bnv[tid] + BN_EPS);
        sScale[tid] = s;
        sShift[tid] = (b2[tid] - bnm[tid]) * s + bnb[tid];
    }
    for (int i = tid; i < NOUT * K / 2; i += 128) {
        int byte = i * 4;
        int row = byte >> 7, kb = byte & 127;
        uint32_t off = (uint32_t)row * SPB + kb;
        sts32(wHi + off, ((const uint32_t*)W2hi)[i]);
        sts32(wLo + off, ((const uint32_t*)W2lo)[i]);
    }
    for (int i = tid; i < 128 * 32; i += 128) {
        int row = i >> 5, w = i & 31;
        uint32_t h = 0, l = 0;
        if (base + row < N_NODES) {
            h = ((const uint32_t*)AGhi)[(size_t)(base + row) * 32 + w];
            l = ((const uint32_t*)AGlo)[(size_t)(base + row) * 32 + w];
        }
        uint32_t off = (uint32_t)row * SPB + w * 4;
        sts32(aHi + off, h);
        sts32(aLo + off, l);
    }
    __syncthreads();

    float acc[2][NT][4];
#pragma unroll
    for (int t = 0; t < 2; t++)
#pragma unroll
        for (int n = 0; n < NT; n++)
#pragma unroll
            for (int j = 0; j < 4; j++) acc[t][n][j] = 0.f;

    const int arow = warp * 32 + (lane & 15);
    const int ahalf = lane >> 4;
    const int brow = lane & 7;
    const int bhalf = (lane >> 3) & 1;

#pragma unroll
    for (int s = 0; s < 3; s++) {
        uint32_t Ab = (s == 2) ? aLo : aHi;
        uint32_t Wb = (s == 1) ? wLo : wHi;
#pragma unroll
        for (int k16 = 0; k16 < 4; k16++) {
            uint32_t kbyte = (uint32_t)(k16 * 32);
            uint32_t af0[4], af1[4];
            ldsm4(af0, Ab + (uint32_t)arow * SPB + kbyte + ahalf * 16);
            ldsm4(af1, Ab + (uint32_t)(arow + 16) * SPB + kbyte + ahalf * 16);
#pragma unroll
            for (int n8 = 0; n8 < NT; n8++) {
                uint32_t bf[2];
                ldsm2(bf, Wb + (uint32_t)(n8 * 8 + brow) * SPB + kbyte + bhalf * 16);
                mma_bf16(acc[0][n8], af0, bf);
                mma_bf16(acc[1][n8], af1, bf);
            }
        }
    }

    const int r_in_warp = lane >> 2;
    const int cpair = (lane & 3) * 2;
#pragma unroll
    for (int t = 0; t < 2; t++) {
#pragma unroll
        for (int n8 = 0; n8 < NT; n8++) {
            int c = n8 * 8 + cpair;
            acc[t][n8][0] = fmaxf(acc[t][n8][0] * sScale[c] + sShift[c], 0.f);
            acc[t][n8][1] = fmaxf(acc[t][n8][1] * sScale[c + 1] + sShift[c + 1], 0.f);
            acc[t][n8][2] = fmaxf(acc[t][n8][2] * sScale[c] + sShift[c], 0.f);
            acc[t][n8][3] = fmaxf(acc[t][n8][3] * sScale[c + 1] + sShift[c + 1], 0.f);
        }
    }

    if (!CHAIN) {
#pragma unroll
        for (int t = 0; t < 2; t++) {
            int row0 = base + warp * 32 + t * 16 + r_in_warp;
            int row1 = row0 + 8;
#pragma unroll
            for (int n8 = 0; n8 < NT; n8++) {
                int c = n8 * 8 + cpair;
                if (row0 < N_NODES) *(float2*)(OUT + (size_t)row0 * NOUT + c) = make_float2(acc[t][n8][0], acc[t][n8][1]);
                if (row1 < N_NODES) *(float2*)(OUT + (size_t)row1 * NOUT + c) = make_float2(acc[t][n8][2], acc[t][n8][3]);
            }
        }
        return;
    }

    __syncthreads();
#pragma unroll
    for (int t = 0; t < 2; t++) {
        int rl0 = warp * 32 + t * 16 + r_in_warp;
        int rl1 = rl0 + 8;
#pragma unroll
        for (int n8 = 0; n8 < NT; n8++) {
            int cb = (n8 * 8 + cpair) * 2;
            uint32_t h, l;
            split2(acc[t][n8][0], acc[t][n8][1], h, l);
            sts32(aHi + (uint32_t)rl0 * SPB + cb, h);
            sts32(aLo + (uint32_t)rl0 * SPB + cb, l);
            split2(acc[t][n8][2], acc[t][n8][3], h, l);
            sts32(aHi + (uint32_t)rl1 * SPB + cb, h);
            sts32(aLo + (uint32_t)rl1 * SPB + cb, l);
        }
    }
    for (int i = tid; i < 64 * K / 2; i += 128) {
        int byte = i * 4;
        int row = byte >> 7, kb = byte & 127;
        uint32_t off = (uint32_t)row * SPB + kb;
        sts32(wHi + off, ((const uint32_t*)W1hi)[i]);
        sts32(wLo + off, ((const uint32_t*)W1lo)[i]);
    }
    __syncthreads();

    float acc2[2][8][4];
#pragma unroll
    for (int t = 0; t < 2; t++)
#pragma unroll
        for (int n = 0; n < 8; n++)
#pragma unroll
            for (int j = 0; j < 4; j++) acc2[t][n][j] = 0.f;

#pragma unroll
    for (int s = 0; s < 3; s++) {
        uint32_t Ab = (s == 2) ? aLo : aHi;
        uint32_t Wb = (s == 1) ? wLo : wHi;
#pragma unroll
        for (int k16 = 0; k16 < 4; k16++) {
            uint32_t kbyte = (uint32_t)(k16 * 32);
            uint32_t af0[4], af1[4];
            ldsm4(af0, Ab + (uint32_t)arow * SPB + kbyte + ahalf * 16);
            ldsm4(af1, Ab + (uint32_t)(arow + 16) * SPB + kbyte + ahalf * 16);
#pragma unroll
            for (int n8 = 0; n8 < 8; n8++) {
                uint32_t bf[2];
                ldsm2(bf, Wb + (uint32_t)(n8 * 8 + brow) * SPB + kbyte + bhalf * 16);
                mma_bf16(acc2[0][n8], af0, bf);
                mma_bf16(acc2[1][n8], af1, bf);
            }
        }
    }
#pragma unroll
    for (int t = 0; t < 2; t++) {
        int row0 = base + warp * 32 + t * 16 + r_in_warp;
        int row1 = row0 + 8;
#pragma unroll
        for (int n8 = 0; n8 < 8; n8++) {
            int c = n8 * 8 + cpair;
            if (row0 < N_NODES) *(float2*)(OUT + (size_t)row0 * 64 + c) = make_float2(acc2[t][n8][0], acc2[t][n8][1]);
            if (row1 < N_NODES) *(float2*)(OUT + (size_t)row1 * 64 + c) = make_float2(acc2[t][n8][2], acc2[t][n8][3]);
        }
    }
}

// ================= pool =================
#define PB_NODES 64
__global__ void pool_kernel(const float* __restrict__ F, const int* __restrict__ batch,
                            float* __restrict__ sums, int* __restrict__ cnts) {
    __shared__ int sb[PB_NODES];
    const int start = blockIdx.x * PB_NODES;
    const int nn = min(PB_NODES, N_NODES - start);
    const int tid = threadIdx.x;   // 96
    if (tid < nn) sb[tid] = batch[start + tid];
    __syncthreads();
    if (tid == 0) {
        int cur = sb[0], c = 0;
        for (int n = 0; n < nn; n++) {
            int g = sb[n];
            if (g != cur) { atomicAdd(&cnts[cur], c); cur = g; c = 0; }
            c++;
        }
        atomicAdd(&cnts[cur], c);
    }
    int cur = sb[0];
    float acc = 0.f;
    for (int n = 0; n < nn; n++) {
        int g = sb[n];
        float v = F[(size_t)(start + n) * 96 + tid];
        if (g != cur) { atomicAdd(&sums[cur * 96 + tid], acc); acc = 0.f; cur = g; }
        acc += v;
    }
    atomicAdd(&sums[cur * 96 + tid], acc);
}
__global__ void finalize_kernel(const float* __restrict__ sums, const int* __restrict__ cnts,
                                float* __restrict__ out) {
    int i = blockIdx.x * blockDim.x + threadIdx.x;
    if (i >= N_GRAPHS * 96) return;
    float c = fmaxf((float)cnts[i / 96], 1.f);
    out[i] = sums[i] / c;
}

// ================= launch =================
extern "C" void kernel_launch(void* const* d_in, const int* in_sizes, int n_in,
                              void* d_out, int out_size) {
    const float* x     = (const float*)d_in[0];
    const void*  ei    = d_in[1];
    const void*  batch = d_in[2];
    const float* P[24];
    for (int i = 0; i < 24; i++) P[i] = (const float*)d_in[3 + i];

    float *y, *f, *sums;
    __nv_bfloat16 *aghi, *aglo, *whi, *wlo;
    int *cnts, *b32, *flags;
    int *deg, *rowptr, *cursor, *colv;
    unsigned long long* sstate;
    cudaGetSymbolAddress((void**)&y,      g_y);
    cudaGetSymbolAddress((void**)&aghi,   g_aghi);
    cudaGetSymbolAddress((void**)&aglo,   g_aglo);
    cudaGetSymbolAddress((void**)&f,      g_f);
    cudaGetSymbolAddress((void**)&sums,   g_sums);
    cudaGetSymbolAddress((void**)&cnts,   g_cnts);
    cudaGetSymbolAddress((void**)&b32,    g_batch32);
    cudaGetSymbolAddress((void**)&flags,  g_flags);
    cudaGetSymbolAddress((void**)&deg,    g_deg);
    cudaGetSymbolAddress((void**)&rowptr, g_rowptr);
    cudaGetSymbolAddress((void**)&cursor, g_cursor);
    cudaGetSymbolAddress((void**)&colv,   g_col);
    cudaGetSymbolAddress((void**)&sstate, g_scanstate);
    cudaGetSymbolAddress((void**)&whi,    g_whi);
    cudaGetSymbolAddress((void**)&wlo,    g_wlo);

    const int SM_L0  = (256 + 128) * (136 * 2);   // 104448
    const int SM_F64 = (256 + 128) * (72 * 2);    // 55296
    const int SM_F96 = (256 + 192) * (72 * 2);    // 64512
    cudaFuncSetAttribute((const void*)hgemm_l0, cudaFuncAttributeMaxDynamicSharedMemorySize, SM_L0);
    cudaFuncSetAttribute((const void*)fused_mlp<64, true>,  cudaFuncAttributeMaxDynamicSharedMemorySize, SM_F64);
    cudaFuncSetAttribute((const void*)fused_mlp<96, false>, cudaFuncAttributeMaxDynamicSharedMemorySize, SM_F96);

    const int NB = (N_NODES + 127) / 128;          // 782
    const int GB = (N_NODES * 16 + 255) / 256;     // 6250 (16 lanes per node)

    cudaStream_t s2;
    cudaStreamCreateWithFlags(&s2, cudaStreamNonBlocking);
    cudaEvent_t evFork, evJoin, evFlags;
    cudaEventCreateWithFlags(&evFork, cudaEventDisableTiming);
    cudaEventCreateWithFlags(&evJoin, cudaEventDisableTiming);
    cudaEventCreateWithFlags(&evFlags, cudaEventDisableTiming);

    cudaEventRecord(evFork, 0);
    cudaStreamWaitEvent(s2, evFork, 0);

    // --- branch A (stream 0): CSR build (critical path) ---
    prep_graph_kernel<<<NB_SCAN + 2, 256>>>(ei, batch, flags, deg, sstate);
    cudaEventRecord(evFlags, 0);
    hist_kernel<<<EB, 256>>>(ei, flags, deg);
    scan_onepass_kernel<<<NB_SCAN, SCAN_BS>>>(deg, rowptr, cursor, sstate);
    fill_kernel<<<EB, 256>>>(ei, flags, cursor, colv);

    // --- branch B (s2): weights + layer-0 GEMM + batch convert + pool zero ---
    const int O_W10 = 0, O_W20 = 8192, O_W11 = 12288, O_W21 = 16384, O_W12 = 20480, O_W22 = 24576;
    wsplit_kernel<<<WB, 256, 0, s2>>>(P[0], P[2], P[8], P[10], P[16], P[18], whi, wlo);
    hgemm_l0<<<NB, 128, SM_L0, s2>>>(x, whi + O_W10, wlo + O_W10, y);
    cudaStreamWaitEvent(s2, evFlags, 0);
    side_kernel<<<NBB + 1, 256, 0, s2>>>(batch, flags, b32, sums, cnts);
    cudaEventRecord(evJoin, s2);

    cudaStreamWaitEvent(0, evJoin, 0);

    gather_kernel<<<GB, 256>>>(y, rowptr, colv, P[1], aghi, aglo);
    fused_mlp<64, true><<<NB, 128, SM_F64>>>(aghi, aglo, whi + O_W20, wlo + O_W20,
                                             P[3], P[4], P[5], P[6], P[7],
                                             whi + O_W11, wlo + O_W11, y);
    gather_kernel<<<GB, 256>>>(y, rowptr, colv, P[9], aghi, aglo);
    fused_mlp<64, true><<<NB, 128, SM_F64>>>(aghi, aglo, whi + O_W21, wlo + O_W21,
                                             P[11], P[12], P[13], P[14], P[15],
                                             whi + O_W12, wlo + O_W12, y);
    gather_kernel<<<GB, 256>>>(y, rowptr, colv, P[17], aghi, aglo);
    fused_mlp<96, false><<<NB, 128, SM_F96>>>(aghi, aglo, whi + O_W22, wlo + O_W22,
                                              P[19], P[20], P[21], P[22], P[23],
                                              nullptr, nullptr, f);

    pool_kernel<<<(N_NODES + PB_NODES - 1) / PB_NODES, 96>>>(f, b32, sums, cnts);
    finalize_kernel<<<(N_GRAPHS * 96 + 255) / 256, 256>>>(sums, cnts, (float*)d_out);

    cudaEventDestroy(evFork);
    cudaEventDestroy(evJoin);
    cudaEventDestroy(evFlags);
    cudaStreamDestroy(s2);
}

// round 16
// speedup vs baseline: 1.1566x; 1.0219x over previous
#include <cuda_runtime.h>
#include <cuda_bf16.h>
#include <cstdint>

#define N_NODES 100000
#define N_EDGES 600000
#define N_GRAPHS 64
#define BN_EPS 1e-5f
#define SCAN_BS 256
#define NB_SCAN ((N_NODES + SCAN_BS - 1) / SCAN_BS)   // 391
#define EB2 ((N_EDGES + 511) / 512)                    // 1172 (2 edges/thread)
#define NBB ((N_NODES + 255) / 256)                    // 391
#define WTOT 30720
#define WB ((WTOT + 255) / 256)                        // 120

// ================= helpers =================
__device__ __forceinline__ uint32_t smem_u32(const void* p) {
    uint32_t a;
    asm("{ .reg .u64 t; cvta.to.shared.u64 t, %1; cvt.u32.u64 %0, t; }" : "=r"(a) : "l"(p));
    return a;
}
__device__ __forceinline__ void sts32(uint32_t addr, uint32_t v) {
    asm volatile("st.shared.b32 [%0], %1;" :: "r"(addr), "r"(v));
}
__device__ __forceinline__ void ldsm4(uint32_t r[4], uint32_t a) {
    asm volatile("ldmatrix.sync.aligned.m8n8.x4.shared.b16 {%0,%1,%2,%3}, [%4];"
                 : "=r"(r[0]), "=r"(r[1]), "=r"(r[2]), "=r"(r[3]) : "r"(a));
}
__device__ __forceinline__ void ldsm2(uint32_t r[2], uint32_t a) {
    asm volatile("ldmatrix.sync.aligned.m8n8.x2.shared.b16 {%0,%1}, [%2];"
                 : "=r"(r[0]), "=r"(r[1]) : "r"(a));
}
__device__ __forceinline__ void mma_bf16(float c[4], const uint32_t a[4], const uint32_t b[2]) {
    asm volatile("mma.sync.aligned.m16n8k16.row.col.f32.bf16.bf16.f32 "
                 "{%0,%1,%2,%3}, {%4,%5,%6,%7}, {%8,%9}, {%0,%1,%2,%3};"
                 : "+f"(c[0]), "+f"(c[1]), "+f"(c[2]), "+f"(c[3])
                 : "r"(a[0]), "r"(a[1]), "r"(a[2]), "r"(a[3]), "r"(b[0]), "r"(b[1]));
}
__device__ __forceinline__ void split2(float a, float b, uint32_t& hi, uint32_t& lo) {
    __nv_bfloat16 ha = __float2bfloat16(a), hb = __float2bfloat16(b);
    __nv_bfloat16 la = __float2bfloat16(a - __bfloat162float(ha));
    __nv_bfloat16 lb = __float2bfloat16(b - __bfloat162float(hb));
    __nv_bfloat162 H; H.x = ha; H.y = hb;
    __nv_bfloat162 L; L.x = la; L.y = lb;
    hi = *(uint32_t*)&H; lo = *(uint32_t*)&L;
}
__device__ __forceinline__ uint32_t pack_bf16x2(float a, float b) {
    __nv_bfloat162 h;
    h.x = __float2bfloat16(a);
    h.y = __float2bfloat16(b);
    return *(uint32_t*)&h;
}

// ================= scratch =================
__device__ float g_y[(size_t)N_NODES * 64];
__device__ __nv_bfloat16 g_aghi[(size_t)N_NODES * 64];
__device__ __nv_bfloat16 g_aglo[(size_t)N_NODES * 64];
__device__ __nv_bfloat16 g_f[(size_t)N_NODES * 96];
__device__ float g_sums[N_GRAPHS * 96];
__device__ int   g_cnts[N_GRAPHS];
__device__ int   g_batch32[N_NODES];
__device__ int   g_deg[N_NODES];
__device__ int   g_rowptr[N_NODES + 1];
__device__ int   g_cursor[N_NODES];
__device__ int   g_col[N_EDGES];
__device__ unsigned long long g_scanstate[NB_SCAN];
__device__ int   g_flags[2];
__device__ __nv_bfloat16 g_whi[WTOT];
__device__ __nv_bfloat16 g_wlo[WTOT];

// ================= branch-A prep: detect dtypes + zero deg/scanstate =================
__global__ void prep_graph_kernel(const void* ei, const void* batch, int* flags,
                                  int* __restrict__ deg,
                                  unsigned long long* __restrict__ sstate) {
    int b = blockIdx.x, t = threadIdx.x;
    if (b < NB_SCAN) {
        int i = b * 256 + t;
        if (i < N_NODES) deg[i] = 0;
        if (t == 0) sstate[b] = 0ULL;
    } else {
        __shared__ int ok;
        if (t == 0) ok = 1;
        __syncthreads();
        int which = b - NB_SCAN;
        const void* p = (which == 0) ? ei : batch;
        long long n64_max = (which == 0) ? (long long)N_EDGES : (long long)N_NODES / 2;
        int maxval = (which == 0) ? N_NODES : N_GRAPHS;
        long long idx = (long long)t * (n64_max - 1) / 255;
        long long v = ((const long long*)p)[idx];
        if (v < 0 || v >= maxval) atomicAnd(&ok, 0);
        __syncthreads();
        if (t == 0) flags[which] = ok;
    }
}

// ================= branch-B side work: batch convert + pool zeroing =================
__global__ void side_kernel(const void* batch, const int* flags,
                            int* __restrict__ b32,
                            float* __restrict__ sums, int* __restrict__ cnts) {
    int b = blockIdx.x, t = threadIdx.x;
    if (b < NBB) {
        int i = b * 256 + t;
        if (i >= N_NODES) return;
        if (flags[1]) b32[i] = (int)((const long long*)batch)[i];
        else          b32[i] = ((const int*)batch)[i];
    } else {
        for (int i = t; i < N_GRAPHS * 96; i += 256) sums[i] = 0.f;
        if (t < N_GRAPHS) cnts[t] = 0;
    }
}

// ================= weight split =================
__global__ void wsplit_kernel(const float* w10, const float* w20, const float* w11,
                              const float* w21, const float* w12, const float* w22,
                              __nv_bfloat16* __restrict__ whi, __nv_bfloat16* __restrict__ wlo) {
    int i = blockIdx.x * blockDim.x + threadIdx.x;
    if (i >= WTOT) return;
    const float* src; int K, off;
    if      (i < 8192)  { src = w10; K = 128; off = 0; }
    else if (i < 12288) { src = w20; K = 64;  off = 8192; }
    else if (i < 16384) { src = w11; K = 64;  off = 12288; }
    else if (i < 20480) { src = w21; K = 64;  off = 16384; }
    else if (i < 24576) { src = w12; K = 64;  off = 20480; }
    else                { src = w22; K = 64;  off = 24576; }
    int N = (i < 24576) ? 64 : 96;
    int local = i - off;
    int n = local / K, k = local % K;
    float v = src[k * N + n];
    __nv_bfloat16 h = __float2bfloat16(v);
    whi[i] = h;
    wlo[i] = __float2bfloat16(v - __bfloat162float(h));
}

// ================= deg histogram from raw ei (2 edges/thread) =================
__global__ void hist_kernel(const void* ei, const int* flags, int* __restrict__ deg) {
    int i = (blockIdx.x * blockDim.x + threadIdx.x) * 2;
    if (i >= N_EDGES) return;
    int d0, d1 = -1;
    if (flags[0]) {
        const long long* p = (const long long*)ei + N_EDGES;
        d0 = (int)p[i];
        if (i + 1 < N_EDGES) d1 = (int)p[i + 1];
    } else {
        const int* p = (const int*)ei + N_EDGES;
        d0 = p[i];
        if (i + 1 < N_EDGES) d1 = p[i + 1];
    }
    atomicAdd(&deg[d0], 1);
    if (d1 >= 0) atomicAdd(&deg[d1], 1);
}

// ================= single-pass exclusive scan (decoupled lookback) =================
__global__ void scan_onepass_kernel(const int* __restrict__ deg,
                                    int* __restrict__ rowptr, int* __restrict__ cursor,
                                    unsigned long long* __restrict__ sstate) {
    __shared__ int sm[SCAN_BS];
    __shared__ int s_off;
    int b = blockIdx.x, t = threadIdx.x;
    int i = b * SCAN_BS + t;
    int v = (i < N_NODES) ? deg[i] : 0;
    sm[t] = v;
    __syncthreads();
    for (int off = 1; off < SCAN_BS; off <<= 1) {
        int x = (t >= off) ? sm[t - off] : 0;
        __syncthreads();
        sm[t] += x;
        __syncthreads();
    }
    int total = sm[SCAN_BS - 1];
    if (t == 0) {
        if (b == 0) {
            atomicExch(&sstate[0], (2ULL << 32) | (unsigned)total);
            s_off = 0;
        } else {
            atomicExch(&sstate[b], (1ULL << 32) | (unsigned)total);
            int run = 0;
            int j = b - 1;
            while (true) {
                unsigned long long w = atomicAdd(&sstate[j], 0ULL);
                unsigned st = (unsigned)(w >> 32);
                if (st == 0) { __nanosleep(40); continue; }
                run += (int)(w & 0xffffffffULL);
                if (st == 2) break;
                j--;
            }
            atomicExch(&sstate[b], (2ULL << 32) | (unsigned)(run + total));
            s_off = run;
        }
    }
    __syncthreads();
    int off0 = s_off;
    if (i < N_NODES) {
        int r = off0 + sm[t] - v;
        rowptr[i] = r;
        cursor[i] = r;
    }
    if (i == N_NODES - 1) rowptr[N_NODES] = off0 + sm[t];
}

// ================= fill: CSR column array from raw ei (2 edges/thread) =================
__global__ void fill_kernel(const void* ei, const int* flags,
                            int* __restrict__ cursor, int* __restrict__ col) {
    int e = (blockIdx.x * blockDim.x + threadIdx.x) * 2;
    if (e >= N_EDGES) return;
    int s0, d0, s1 = -1, d1 = -1;
    if (flags[0]) {
        const long long* p = (const long long*)ei;
        s0 = (int)p[e]; d0 = (int)p[N_EDGES + e];
        if (e + 1 < N_EDGES) { s1 = (int)p[e + 1]; d1 = (int)p[N_EDGES + e + 1]; }
    } else {
        const int* p = (const int*)ei;
        s0 = p[e]; d0 = p[N_EDGES + e];
        if (e + 1 < N_EDGES) { s1 = p[e + 1]; d1 = p[N_EDGES + e + 1]; }
    }
    int p0 = atomicAdd(&cursor[d0], 1);
    int p1 = (d1 >= 0) ? atomicAdd(&cursor[d1], 1) : -1;
    col[p0] = s0;
    if (p1 >= 0) col[p1] = s1;
}

// ================= standalone GEMM layer0: Y = X @ W1 (K=128, N=64) =================
__global__ __launch_bounds__(128) void hgemm_l0(const float* __restrict__ X,
                                                const __nv_bfloat16* __restrict__ Whi,
                                                const __nv_bfloat16* __restrict__ Wlo,
                                                float* __restrict__ Y) {
    constexpr int K = 128, N = 64;
    constexpr int SP = K + 8, SPB = SP * 2, NT = N / 8;
    extern __shared__ char dsm[];
    uint32_t aHi = smem_u32(dsm);
    uint32_t aLo = aHi + 128 * SPB;
    uint32_t wHi = aLo + 128 * SPB;
    uint32_t wLo = wHi + N * SPB;

    const int tid = threadIdx.x, warp = tid >> 5, lane = tid & 31;
    const int base = blockIdx.x * 128;

    for (int i = tid; i < N * K / 2; i += 128) {
        int byte = i * 4;
        int row = byte / (K * 2), kb = byte - row * (K * 2);
        uint32_t off = (uint32_t)row * SPB + kb;
        sts32(wHi + off, ((const uint32_t*)Whi)[i]);
        sts32(wLo + off, ((const uint32_t*)Wlo)[i]);
    }
    constexpr int N4 = K / 4;
    for (int i = tid; i < 128 * N4; i += 128) {
        int row = i / N4, c4 = i - row * N4, col = c4 * 4;
        float4 v = make_float4(0.f, 0.f, 0.f, 0.f);
        if (base + row < N_NODES) v = ((const float4*)X)[(size_t)(base + row) * N4 + c4];
        uint32_t h01, l01, h23, l23;
        split2(v.x, v.y, h01, l01);
        split2(v.z, v.w, h23, l23);
        uint32_t off = (uint32_t)row * SPB + col * 2;
        sts32(aHi + off, h01); sts32(aHi + off + 4, h23);
        sts32(aLo + off, l01); sts32(aLo + off + 4, l23);
    }
    __syncthreads();

    float acc[2][NT][4];
#pragma unroll
    for (int t = 0; t < 2; t++)
#pragma unroll
        for (int n = 0; n < NT; n++)
#pragma unroll
            for (int j = 0; j < 4; j++) acc[t][n][j] = 0.f;

    const int arow = warp * 32 + (lane & 15);
    const int ahalf = lane >> 4;
    const int brow = lane & 7;
    const int bhalf = (lane >> 3) & 1;

#pragma unroll
    for (int s = 0; s < 3; s++) {
        uint32_t Ab = (s == 2) ? aLo : aHi;
        uint32_t Wb = (s == 1) ? wLo : wHi;
#pragma unroll
        for (int k16 = 0; k16 < K / 16; k16++) {
            uint32_t kbyte = (uint32_t)(k16 * 16) * 2;
            uint32_t af0[4], af1[4];
            ldsm4(af0, Ab + (uint32_t)arow * SPB + kbyte + ahalf * 16);
            ldsm4(af1, Ab + (uint32_t)(arow + 16) * SPB + kbyte + ahalf * 16);
#pragma unroll
            for (int n8 = 0; n8 < NT; n8++) {
                uint32_t bf[2];
                ldsm2(bf, Wb + (uint32_t)(n8 * 8 + brow) * SPB + kbyte + bhalf * 16);
                mma_bf16(acc[0][n8], af0, bf);
                mma_bf16(acc[1][n8], af1, bf);
            }
        }
    }
    const int r_in_warp = lane >> 2;
    const int cpair = (lane & 3) * 2;
#pragma unroll
    for (int t = 0; t < 2; t++) {
        int row0 = base + warp * 32 + t * 16 + r_in_warp;
        int row1 = row0 + 8;
#pragma unroll
        for (int n8 = 0; n8 < NT; n8++) {
            int col = n8 * 8 + cpair;
            if (row0 < N_NODES) *(float2*)(Y + (size_t)row0 * N + col) = make_float2(acc[t][n8][0], acc[t][n8][1]);
            if (row1 < N_NODES) *(float2*)(Y + (size_t)row1 * N + col) = make_float2(acc[t][n8][2], acc[t][n8][3]);
        }
    }
}

// ================= gather: 2 nodes/warp, float4 lanes, AG = split(ReLU(sum + b1)) =================
__global__ __launch_bounds__(256) void gather_kernel(const float* __restrict__ Y,
                                                     const int* __restrict__ rowptr,
                                                     const int* __restrict__ col,
                                                     const float* __restrict__ b1,
                                                     __nv_bfloat16* __restrict__ AGhi,
                                                     __nv_bfloat16* __restrict__ AGlo) {
    int w = (blockIdx.x * blockDim.x + threadIdx.x) >> 4;
    int lane = threadIdx.x & 15;
    if (w >= N_NODES) return;
    const float4* y4 = (const float4*)Y;
    float4 bias = ((const float4*)b1)[lane];
    int r0 = rowptr[w], r1 = rowptr[w + 1];
    float4 acc = y4[(size_t)w * 16 + lane];
    int e = r0;
    for (; e + 3 < r1; e += 4) {
        int s0 = col[e], s1 = col[e + 1], s2 = col[e + 2], s3 = col[e + 3];
        float4 a = y4[(size_t)s0 * 16 + lane];
        float4 b = y4[(size_t)s1 * 16 + lane];
        float4 c = y4[(size_t)s2 * 16 + lane];
        float4 d = y4[(size_t)s3 * 16 + lane];
        acc.x += (a.x + b.x) + (c.x + d.x);
        acc.y += (a.y + b.y) + (c.y + d.y);
        acc.z += (a.z + b.z) + (c.z + d.z);
        acc.w += (a.w + b.w) + (c.w + d.w);
    }
    if (e + 1 < r1) {
        int s0 = col[e], s1 = col[e + 1];
        float4 a = y4[(size_t)s0 * 16 + lane];
        float4 b = y4[(size_t)s1 * 16 + lane];
        acc.x += a.x + b.x;
        acc.y += a.y + b.y;
        acc.z += a.z + b.z;
        acc.w += a.w + b.w;
        e += 2;
    }
    if (e < r1) {
        int s = col[e];
        float4 a = y4[(size_t)s * 16 + lane];
        acc.x += a.x; acc.y += a.y; acc.z += a.z; acc.w += a.w;
    }
    acc.x = fmaxf(acc.x + bias.x, 0.f);
    acc.y = fmaxf(acc.y + bias.y, 0.f);
    acc.z = fmaxf(acc.z + bias.z, 0.f);
    acc.w = fmaxf(acc.w + bias.w, 0.f);
    uint32_t h01, l01, h23, l23;
    split2(acc.x, acc.y, h01, l01);
    split2(acc.z, acc.w, h23, l23);
    *(uint2*)((uint32_t*)AGhi + (size_t)w * 32 + lane * 2) = make_uint2(h01, h23);
    *(uint2*)((uint32_t*)AGlo + (size_t)w * 32 + lane * 2) = make_uint2(l01, l23);
}

// ================= fused MLP: AG(bf16) @ W2 -> BN+ReLU -> [@W1next -> Y | bf16 out] =================
template <int NOUT, bool CHAIN, bool OUTBF>
__global__ __launch_bounds__(128) void fused_mlp(const __nv_bfloat16* __restrict__ AGhi,
                                                 const __nv_bfloat16* __restrict__ AGlo,
                                                 const __nv_bfloat16* __restrict__ W2hi,
                                                 const __nv_bfloat16* __restrict__ W2lo,
                                                 const float* __restrict__ b2,
                                                 const float* __restrict__ bng,
                                                 const float* __restrict__ bnb,
                                                 const float* __restrict__ bnm,
                                                 const float* __restrict__ bnv,
                                                 const __nv_bfloat16* __restrict__ W1hi,
                                                 const __nv_bfloat16* __restrict__ W1lo,
                                                 void* __restrict__ OUT) {
    constexpr int K = 64;
    constexpr int SP = K + 8, SPB = SP * 2;
    constexpr int NT = NOUT / 8;
    extern __shared__ char dsm[];
    uint32_t aHi = smem_u32(dsm);
    uint32_t aLo = aHi + 128 * SPB;
    uint32_t wHi = aLo + 128 * SPB;
    uint32_t wLo = wHi + NOUT * SPB;
    __shared__ float sScale[NOUT];
    __shared__ float sShift[NOUT];

    const int tid = threadIdx.x, warp = tid >> 5, lane = tid & 31;
    const int base = blockIdx.x * 128;

    if (tid < NOUT) {
        float s = bng[tid] * rsqrtf(bnv[tid] + BN_EPS);
        sScale[tid] = s;
        sShift[tid] = (b2[tid] - bnm[tid]) * s + bnb[tid];
    }
    for (int i = tid; i < NOUT * K / 2; i += 128) {
        int byte = i * 4;
        int row = byte >> 7, kb = byte & 127;
        uint32_t off = (uint32_t)row * SPB + kb;
        sts32(wHi + off, ((const uint32_t*)W2hi)[i]);
        sts32(wLo + off, ((const uint32_t*)W2lo)[i]);
    }
    for (int i = tid; i < 128 * 32; i += 128) {
        int row = i >> 5, w = i & 31;
        uint32_t h = 0, l = 0;
        if (base + row < N_NODES) {
            h = ((const uint32_t*)AGhi)[(size_t)(base + row) * 32 + w];
            l = ((const uint32_t*)AGlo)[(size_t)(base + row) * 32 + w];
        }
        uint32_t off = (uint32_t)row * SPB + w * 4;
        sts32(aHi + off, h);
        sts32(aLo + off, l);
    }
    __syncthreads();

    float acc[2][NT][4];
#pragma unroll
    for (int t = 0; t < 2; t++)
#pragma unroll
        for (int n = 0; n < NT; n++)
#pragma unroll
            for (int j = 0; j < 4; j++) acc[t][n][j] = 0.f;

    const int arow = warp * 32 + (lane & 15);
    const int ahalf = lane >> 4;
    const int brow = lane & 7;
    const int bhalf = (lane >> 3) & 1;

#pragma unroll
    for (int s = 0; s < 3; s++) {
        uint32_t Ab = (s == 2) ? aLo : aHi;
        uint32_t Wb = (s == 1) ? wLo : wHi;
#pragma unroll
        for (int k16 = 0; k16 < 4; k16++) {
            uint32_t kbyte = (uint32_t)(k16 * 32);
            uint32_t af0[4], af1[4];
            ldsm4(af0, Ab + (uint32_t)arow * SPB + kbyte + ahalf * 16);
            ldsm4(af1, Ab + (uint32_t)(arow + 16) * SPB + kbyte + ahalf * 16);
#pragma unroll
            for (int n8 = 0; n8 < NT; n8++) {
                uint32_t bf[2];
                ldsm2(bf, Wb + (uint32_t)(n8 * 8 + brow) * SPB + kbyte + bhalf * 16);
                mma_bf16(acc[0][n8], af0, bf);
                mma_bf16(acc[1][n8], af1, bf);
            }
        }
    }

    const int r_in_warp = lane >> 2;
    const int cpair = (lane & 3) * 2;
#pragma unroll
    for (int t = 0; t < 2; t++) {
#pragma unroll
        for (int n8 = 0; n8 < NT; n8++) {
            int c = n8 * 8 + cpair;
            acc[t][n8][0] = fmaxf(acc[t][n8][0] * sScale[c] + sShift[c], 0.f);
            acc[t][n8][1] = fmaxf(acc[t][n8][1] * sScale[c + 1] + sShift[c + 1], 0.f);
            acc[t][n8][2] = fmaxf(acc[t][n8][2] * sScale[c] + sShift[c], 0.f);
            acc[t][n8][3] = fmaxf(acc[t][n8][3] * sScale[c + 1] + sShift[c + 1], 0.f);
        }
    }

    if (!CHAIN) {
#pragma unroll
        for (int t = 0; t < 2; t++) {
            int row0 = base + warp * 32 + t * 16 + r_in_warp;
            int row1 = row0 + 8;
#pragma unroll
            for (int n8 = 0; n8 < NT; n8++) {
                int c = n8 * 8 + cpair;
                if (OUTBF) {
                    __nv_bfloat16* O = (__nv_bfloat16*)OUT;
                    if (row0 < N_NODES)
                        *(uint32_t*)(O + (size_t)row0 * NOUT + c) = pack_bf16x2(acc[t][n8][0], acc[t][n8][1]);
                    if (row1 < N_NODES)
                        *(uint32_t*)(O + (size_t)row1 * NOUT + c) = pack_bf16x2(acc[t][n8][2], acc[t][n8][3]);
                } else {
                    float* O = (float*)OUT;
                    if (row0 < N_NODES) *(float2*)(O + (size_t)row0 * NOUT + c) = make_float2(acc[t][n8][0], acc[t][n8][1]);
                    if (row1 < N_NODES) *(float2*)(O + (size_t)row1 * NOUT + c) = make_float2(acc[t][n8][2], acc[t][n8][3]);
                }
            }
        }
        return;
    }

    __syncthreads();
#pragma unroll
    for (int t = 0; t < 2; t++) {
        int rl0 = warp * 32 + t * 16 + r_in_warp;
        int rl1 = rl0 + 8;
#pragma unroll
        for (int n8 = 0; n8 < NT; n8++) {
            int cb = (n8 * 8 + cpair) * 2;
            uint32_t h, l;
            split2(acc[t][n8][0], acc[t][n8][1], h, l);
            sts32(aHi + (uint32_t)rl0 * SPB + cb, h);
            sts32(aLo + (uint32_t)rl0 * SPB + cb, l);
            split2(acc[t][n8][2], acc[t][n8][3], h, l);
            sts32(aHi + (uint32_t)rl1 * SPB + cb, h);
            sts32(aLo + (uint32_t)rl1 * SPB + cb, l);
        }
    }
    for (int i = tid; i < 64 * K / 2; i += 128) {
        int byte = i * 4;
        int row = byte >> 7, kb = byte & 127;
        uint32_t off = (uint32_t)row * SPB + kb;
        sts32(wHi + off, ((const uint32_t*)W1hi)[i]);
        sts32(wLo + off, ((const uint32_t*)W1lo)[i]);
    }
    __syncthreads();

    float acc2[2][8][4];
#pragma unroll
    for (int t = 0; t < 2; t++)
#pragma unroll
        for (int n = 0; n < 8; n++)
#pragma unroll
            for (int j = 0; j < 4; j++) acc2[t][n][j] = 0.f;

#pragma unroll
    for (int s = 0; s < 3; s++) {
        uint32_t Ab = (s == 2) ? aLo : aHi;
        uint32_t Wb = (s == 1) ? wLo : wHi;
#pragma unroll
        for (int k16 = 0; k16 < 4; k16++) {
            uint32_t kbyte = (uint32_t)(k16 * 32);
            uint32_t af0[4], af1[4];
            ldsm4(af0, Ab + (uint32_t)arow * SPB + kbyte + ahalf * 16);
            ldsm4(af1, Ab + (uint32_t)(arow + 16) * SPB + kbyte + ahalf * 16);
#pragma unroll
            for (int n8 = 0; n8 < 8; n8++) {
                uint32_t bf[2];
                ldsm2(bf, Wb + (uint32_t)(n8 * 8 + brow) * SPB + kbyte + bhalf * 16);
                mma_bf16(acc2[0][n8], af0, bf);
                mma_bf16(acc2[1][n8], af1, bf);
            }
        }
    }
    float* O = (float*)OUT;
#pragma unroll
    for (int t = 0; t < 2; t++) {
        int row0 = base + warp * 32 + t * 16 + r_in_warp;
        int row1 = row0 + 8;
#pragma unroll
        for (int n8 = 0; n8 < 8; n8++) {
            int c = n8 * 8 + cpair;
            if (row0 < N_NODES) *(float2*)(O + (size_t)row0 * 64 + c) = make_float2(acc2[t][n8][0], acc2[t][n8][1]);
            if (row1 < N_NODES) *(float2*)(O + (size_t)row1 * 64 + c) = make_float2(acc2[t][n8][2], acc2[t][n8][3]);
        }
    }
}

// ================= pool (reads bf16 features) =================
#define PB_NODES 64
__global__ void pool_kernel(const __nv_bfloat16* __restrict__ F, const int* __restrict__ batch,
                            float* __restrict__ sums, int* __restrict__ cnts) {
    __shared__ int sb[PB_NODES];
    const int start = blockIdx.x * PB_NODES;
    const int nn = min(PB_NODES, N_NODES - start);
    const int tid = threadIdx.x;   // 96
    if (tid < nn) sb[tid] = batch[start + tid];
    __syncthreads();
    if (tid == 0) {
        int cur = sb[0], c = 0;
        for (int n = 0; n < nn; n++) {
            int g = sb[n];
            if (g != cur) { atomicAdd(&cnts[cur], c); cur = g; c = 0; }
            c++;
        }
        atomicAdd(&cnts[cur], c);
    }
    int cur = sb[0];
    float acc = 0.f;
    for (int n = 0; n < nn; n++) {
        int g = sb[n];
        float v = __bfloat162float(F[(size_t)(start + n) * 96 + tid]);
        if (g != cur) { atomicAdd(&sums[cur * 96 + tid], acc); acc = 0.f; cur = g; }
        acc += v;
    }
    atomicAdd(&sums[cur * 96 + tid], acc);
}
__global__ void finalize_kernel(const float* __restrict__ sums, const int* __restrict__ cnts,
                                float* __restrict__ out) {
    int i = blockIdx.x * blockDim.x + threadIdx.x;
    if (i >= N_GRAPHS * 96) return;
    float c = fmaxf((float)cnts[i / 96], 1.f);
    out[i] = sums[i] / c;
}

// ================= launch =================
extern "C" void kernel_launch(void* const* d_in, const int* in_sizes, int n_in,
                              void* d_out, int out_size) {
    const float* x     = (const float*)d_in[0];
    const void*  ei    = d_in[1];
    const void*  batch = d_in[2];
    const float* P[24];
    for (int i = 0; i < 24; i++) P[i] = (const float*)d_in[3 + i];

    float *y, *sums;
    __nv_bfloat16 *aghi, *aglo, *whi, *wlo, *f;
    int *cnts, *b32, *flags;
    int *deg, *rowptr, *cursor, *colv;
    unsigned long long* sstate;
    cudaGetSymbolAddress((void**)&y,      g_y);
    cudaGetSymbolAddress((void**)&aghi,   g_aghi);
    cudaGetSymbolAddress((void**)&aglo,   g_aglo);
    cudaGetSymbolAddress((void**)&f,      g_f);
    cudaGetSymbolAddress((void**)&sums,   g_sums);
    cudaGetSymbolAddress((void**)&cnts,   g_cnts);
    cudaGetSymbolAddress((void**)&b32,    g_batch32);
    cudaGetSymbolAddress((void**)&flags,  g_flags);
    cudaGetSymbolAddress((void**)&deg,    g_deg);
    cudaGetSymbolAddress((void**)&rowptr, g_rowptr);
    cudaGetSymbolAddress((void**)&cursor, g_cursor);
    cudaGetSymbolAddress((void**)&colv,   g_col);
    cudaGetSymbolAddress((void**)&sstate, g_scanstate);
    cudaGetSymbolAddress((void**)&whi,    g_whi);
    cudaGetSymbolAddress((void**)&wlo,    g_wlo);

    const int SM_L0  = (256 + 128) * (136 * 2);   // 104448
    const int SM_F64 = (256 + 128) * (72 * 2);    // 55296
    const int SM_F96 = (256 + 192) * (72 * 2);    // 64512
    cudaFuncSetAttribute((const void*)hgemm_l0, cudaFuncAttributeMaxDynamicSharedMemorySize, SM_L0);
    cudaFuncSetAttribute((const void*)fused_mlp<64, true, false>,  cudaFuncAttributeMaxDynamicSharedMemorySize, SM_F64);
    cudaFuncSetAttribute((const void*)fused_mlp<96, false, true>,  cudaFuncAttributeMaxDynamicSharedMemorySize, SM_F96);

    const int NB = (N_NODES + 127) / 128;          // 782
    const int GB = (N_NODES * 16 + 255) / 256;     // 6250

    cudaStream_t s2;
    cudaStreamCreateWithFlags(&s2, cudaStreamNonBlocking);
    cudaEvent_t evFork, evJoin, evFlags;
    cudaEventCreateWithFlags(&evFork, cudaEventDisableTiming);
    cudaEventCreateWithFlags(&evJoin, cudaEventDisableTiming);
    cudaEventCreateWithFlags(&evFlags, cudaEventDisableTiming);

    cudaEventRecord(evFork, 0);
    cudaStreamWaitEvent(s2, evFork, 0);

    // --- branch A (stream 0): CSR build (critical path) ---
    prep_graph_kernel<<<NB_SCAN + 2, 256>>>(ei, batch, flags, deg, sstate);
    cudaEventRecord(evFlags, 0);
    hist_kernel<<<EB2, 256>>>(ei, flags, deg);
    scan_onepass_kernel<<<NB_SCAN, SCAN_BS>>>(deg, rowptr, cursor, sstate);
    fill_kernel<<<EB2, 256>>>(ei, flags, cursor, colv);

    // --- branch B (s2): weights + layer-0 GEMM + batch convert + pool zero ---
    const int O_W10 = 0, O_W20 = 8192, O_W11 = 12288, O_W21 = 16384, O_W12 = 20480, O_W22 = 24576;
    wsplit_kernel<<<WB, 256, 0, s2>>>(P[0], P[2], P[8], P[10], P[16], P[18], whi, wlo);
    hgemm_l0<<<NB, 128, SM_L0, s2>>>(x, whi + O_W10, wlo + O_W10, y);
    cudaStreamWaitEvent(s2, evFlags, 0);
    side_kernel<<<NBB + 1, 256, 0, s2>>>(batch, flags, b32, sums, cnts);
    cudaEventRecord(evJoin, s2);

    cudaStreamWaitEvent(0, evJoin, 0);

    gather_kernel<<<GB, 256>>>(y, rowptr, colv, P[1], aghi, aglo);
    fused_mlp<64, true, false><<<NB, 128, SM_F64>>>(aghi, aglo, whi + O_W20, wlo + O_W20,
                                                    P[3], P[4], P[5], P[6], P[7],
                                                    whi + O_W11, wlo + O_W11, y);
    gather_kernel<<<GB, 256>>>(y, rowptr, colv, P[9], aghi, aglo);
    fused_mlp<64, true, false><<<NB, 128, SM_F64>>>(aghi, aglo, whi + O_W21, wlo + O_W21,
                                                    P[11], P[12], P[13], P[14], P[15],
                                                    whi + O_W12, wlo + O_W12, y);
    gather_kernel<<<GB, 256>>>(y, rowptr, colv, P[17], aghi, aglo);
    fused_mlp<96, false, true><<<NB, 128, SM_F96>>>(aghi, aglo, whi + O_W22, wlo + O_W22,
                                                    P[19], P[20], P[21], P[22], P[23],
                                                    nullptr, nullptr, f);

    pool_kernel<<<(N_NODES + PB_NODES - 1) / PB_NODES, 96>>>(f, b32, sums, cnts);
    finalize_kernel<<<(N_GRAPHS * 96 + 255) / 256, 256>>>(sums, cnts, (float*)d_out);

    cudaEventDestroy(evFork);
    cudaEventDestroy(evJoin);
    cudaEventDestroy(evFlags);
    cudaStreamDestroy(s2);
}

// round 17
// speedup vs baseline: 1.1601x; 1.0030x over previous
#include <cuda_runtime.h>
#include <cuda_bf16.h>
#include <cstdint>

#define N_NODES 100000
#define N_EDGES 600000
#define N_GRAPHS 64
#define BN_EPS 1e-5f
#define SCAN_BS 256
#define NB_SCAN ((N_NODES + SCAN_BS - 1) / SCAN_BS)   // 391
#define EB4 ((N_EDGES + 1023) / 1024)                  // 586 (4 edges/thread)
#define NBB ((N_NODES + 255) / 256)                    // 391
#define WTOT 30720
#define WB ((WTOT + 255) / 256)                        // 120

// ================= helpers =================
__device__ __forceinline__ uint32_t smem_u32(const void* p) {
    uint32_t a;
    asm("{ .reg .u64 t; cvta.to.shared.u64 t, %1; cvt.u32.u64 %0, t; }" : "=r"(a) : "l"(p));
    return a;
}
__device__ __forceinline__ void sts32(uint32_t addr, uint32_t v) {
    asm volatile("st.shared.b32 [%0], %1;" :: "r"(addr), "r"(v));
}
__device__ __forceinline__ void ldsm4(uint32_t r[4], uint32_t a) {
    asm volatile("ldmatrix.sync.aligned.m8n8.x4.shared.b16 {%0,%1,%2,%3}, [%4];"
                 : "=r"(r[0]), "=r"(r[1]), "=r"(r[2]), "=r"(r[3]) : "r"(a));
}
__device__ __forceinline__ void ldsm2(uint32_t r[2], uint32_t a) {
    asm volatile("ldmatrix.sync.aligned.m8n8.x2.shared.b16 {%0,%1}, [%2];"
                 : "=r"(r[0]), "=r"(r[1]) : "r"(a));
}
__device__ __forceinline__ void mma_bf16(float c[4], const uint32_t a[4], const uint32_t b[2]) {
    asm volatile("mma.sync.aligned.m16n8k16.row.col.f32.bf16.bf16.f32 "
                 "{%0,%1,%2,%3}, {%4,%5,%6,%7}, {%8,%9}, {%0,%1,%2,%3};"
                 : "+f"(c[0]), "+f"(c[1]), "+f"(c[2]), "+f"(c[3])
                 : "r"(a[0]), "r"(a[1]), "r"(a[2]), "r"(a[3]), "r"(b[0]), "r"(b[1]));
}
__device__ __forceinline__ void split2(float a, float b, uint32_t& hi, uint32_t& lo) {
    __nv_bfloat16 ha = __float2bfloat16(a), hb = __float2bfloat16(b);
    __nv_bfloat16 la = __float2bfloat16(a - __bfloat162float(ha));
    __nv_bfloat16 lb = __float2bfloat16(b - __bfloat162float(hb));
    __nv_bfloat162 H; H.x = ha; H.y = hb;
    __nv_bfloat162 L; L.x = la; L.y = lb;
    hi = *(uint32_t*)&H; lo = *(uint32_t*)&L;
}
__device__ __forceinline__ uint32_t pack_bf16x2(float a, float b) {
    __nv_bfloat162 h;
    h.x = __float2bfloat16(a);
    h.y = __float2bfloat16(b);
    return *(uint32_t*)&h;
}
__device__ __forceinline__ void unpack8(uint4 v, float* f) {
    __nv_bfloat162 p;
    p = *(__nv_bfloat162*)&v.x; f[0] = __bfloat162float(p.x); f[1] = __bfloat162float(p.y);
    p = *(__nv_bfloat162*)&v.y; f[2] = __bfloat162float(p.x); f[3] = __bfloat162float(p.y);
    p = *(__nv_bfloat162*)&v.z; f[4] = __bfloat162float(p.x); f[5] = __bfloat162float(p.y);
    p = *(__nv_bfloat162*)&v.w; f[6] = __bfloat162float(p.x); f[7] = __bfloat162float(p.y);
}

// ================= scratch =================
__device__ __nv_bfloat16 g_y[(size_t)N_NODES * 64];
__device__ __nv_bfloat16 g_aghi[(size_t)N_NODES * 64];
__device__ __nv_bfloat16 g_aglo[(size_t)N_NODES * 64];
__device__ __nv_bfloat16 g_f[(size_t)N_NODES * 96];
__device__ float g_sums[N_GRAPHS * 96];
__device__ int   g_cnts[N_GRAPHS];
__device__ int   g_batch32[N_NODES];
__device__ int   g_deg[N_NODES];
__device__ int   g_rowptr[N_NODES + 1];
__device__ int   g_cursor[N_NODES];
__device__ int   g_col[N_EDGES];
__device__ unsigned long long g_scanstate[NB_SCAN];
__device__ int   g_flags[2];
__device__ __nv_bfloat16 g_whi[WTOT];
__device__ __nv_bfloat16 g_wlo[WTOT];

// ================= branch-A prep =================
__global__ void prep_graph_kernel(const void* ei, const void* batch, int* flags,
                                  int* __restrict__ deg,
                                  unsigned long long* __restrict__ sstate) {
    int b = blockIdx.x, t = threadIdx.x;
    if (b < NB_SCAN) {
        int i = b * 256 + t;
        if (i < N_NODES) deg[i] = 0;
        if (t == 0) sstate[b] = 0ULL;
    } else {
        __shared__ int ok;
        if (t == 0) ok = 1;
        __syncthreads();
        int which = b - NB_SCAN;
        const void* p = (which == 0) ? ei : batch;
        long long n64_max = (which == 0) ? (long long)N_EDGES : (long long)N_NODES / 2;
        int maxval = (which == 0) ? N_NODES : N_GRAPHS;
        long long idx = (long long)t * (n64_max - 1) / 255;
        long long v = ((const long long*)p)[idx];
        if (v < 0 || v >= maxval) atomicAnd(&ok, 0);
        __syncthreads();
        if (t == 0) flags[which] = ok;
    }
}

// ================= branch-B side work =================
__global__ void side_kernel(const void* batch, const int* flags,
                            int* __restrict__ b32,
                            float* __restrict__ sums, int* __restrict__ cnts) {
    int b = blockIdx.x, t = threadIdx.x;
    if (b < NBB) {
        int i = b * 256 + t;
        if (i >= N_NODES) return;
        if (flags[1]) b32[i] = (int)((const long long*)batch)[i];
        else          b32[i] = ((const int*)batch)[i];
    } else {
        for (int i = t; i < N_GRAPHS * 96; i += 256) sums[i] = 0.f;
        if (t < N_GRAPHS) cnts[t] = 0;
    }
}

// ================= weight split =================
__global__ void wsplit_kernel(const float* w10, const float* w20, const float* w11,
                              const float* w21, const float* w12, const float* w22,
                              __nv_bfloat16* __restrict__ whi, __nv_bfloat16* __restrict__ wlo) {
    int i = blockIdx.x * blockDim.x + threadIdx.x;
    if (i >= WTOT) return;
    const float* src; int K, off;
    if      (i < 8192)  { src = w10; K = 128; off = 0; }
    else if (i < 12288) { src = w20; K = 64;  off = 8192; }
    else if (i < 16384) { src = w11; K = 64;  off = 12288; }
    else if (i < 20480) { src = w21; K = 64;  off = 16384; }
    else if (i < 24576) { src = w12; K = 64;  off = 20480; }
    else                { src = w22; K = 64;  off = 24576; }
    int N = (i < 24576) ? 64 : 96;
    int local = i - off;
    int n = local / K, k = local % K;
    float v = src[k * N + n];
    __nv_bfloat16 h = __float2bfloat16(v);
    whi[i] = h;
    wlo[i] = __float2bfloat16(v - __bfloat162float(h));
}

// ================= deg histogram (4 edges/thread) =================
__global__ void hist_kernel(const void* ei, const int* flags, int* __restrict__ deg) {
    int i = (blockIdx.x * blockDim.x + threadIdx.x) * 4;
    if (i >= N_EDGES) return;
    int n = min(4, N_EDGES - i);
    if (flags[0]) {
        const long long* p = (const long long*)ei + N_EDGES;
#pragma unroll
        for (int j = 0; j < 4; j++)
            if (j < n) atomicAdd(&deg[(int)p[i + j]], 1);
    } else {
        const int* p = (const int*)ei + N_EDGES;
#pragma unroll
        for (int j = 0; j < 4; j++)
            if (j < n) atomicAdd(&deg[p[i + j]], 1);
    }
}

// ================= single-pass exclusive scan =================
__global__ void scan_onepass_kernel(const int* __restrict__ deg,
                                    int* __restrict__ rowptr, int* __restrict__ cursor,
                                    unsigned long long* __restrict__ sstate) {
    __shared__ int sm[SCAN_BS];
    __shared__ int s_off;
    int b = blockIdx.x, t = threadIdx.x;
    int i = b * SCAN_BS + t;
    int v = (i < N_NODES) ? deg[i] : 0;
    sm[t] = v;
    __syncthreads();
    for (int off = 1; off < SCAN_BS; off <<= 1) {
        int x = (t >= off) ? sm[t - off] : 0;
        __syncthreads();
        sm[t] += x;
        __syncthreads();
    }
    int total = sm[SCAN_BS - 1];
    if (t == 0) {
        if (b == 0) {
            atomicExch(&sstate[0], (2ULL << 32) | (unsigned)total);
            s_off = 0;
        } else {
            atomicExch(&sstate[b], (1ULL << 32) | (unsigned)total);
            int run = 0;
            int j = b - 1;
            while (true) {
                unsigned long long w = atomicAdd(&sstate[j], 0ULL);
                unsigned st = (unsigned)(w >> 32);
                if (st == 0) { __nanosleep(40); continue; }
                run += (int)(w & 0xffffffffULL);
                if (st == 2) break;
                j--;
            }
            atomicExch(&sstate[b], (2ULL << 32) | (unsigned)(run + total));
            s_off = run;
        }
    }
    __syncthreads();
    int off0 = s_off;
    if (i < N_NODES) {
        int r = off0 + sm[t] - v;
        rowptr[i] = r;
        cursor[i] = r;
    }
    if (i == N_NODES - 1) rowptr[N_NODES] = off0 + sm[t];
}

// ================= fill (4 edges/thread) =================
__global__ void fill_kernel(const void* ei, const int* flags,
                            int* __restrict__ cursor, int* __restrict__ col) {
    int e = (blockIdx.x * blockDim.x + threadIdx.x) * 4;
    if (e >= N_EDGES) return;
    int n = min(4, N_EDGES - e);
    int s[4], d[4];
    if (flags[0]) {
        const long long* p = (const long long*)ei;
#pragma unroll
        for (int j = 0; j < 4; j++)
            if (j < n) { s[j] = (int)p[e + j]; d[j] = (int)p[N_EDGES + e + j]; }
    } else {
        const int* p = (const int*)ei;
#pragma unroll
        for (int j = 0; j < 4; j++)
            if (j < n) { s[j] = p[e + j]; d[j] = p[N_EDGES + e + j]; }
    }
    int pos[4];
#pragma unroll
    for (int j = 0; j < 4; j++)
        if (j < n) pos[j] = atomicAdd(&cursor[d[j]], 1);
#pragma unroll
    for (int j = 0; j < 4; j++)
        if (j < n) col[pos[j]] = s[j];
}

// ================= standalone GEMM layer0: Y(bf16) = X @ W1 (K=128, N=64) =================
__global__ __launch_bounds__(128) void hgemm_l0(const float* __restrict__ X,
                                                const __nv_bfloat16* __restrict__ Whi,
                                                const __nv_bfloat16* __restrict__ Wlo,
                                                __nv_bfloat16* __restrict__ Y) {
    constexpr int K = 128, N = 64;
    constexpr int SP = K + 8, SPB = SP * 2, NT = N / 8;
    extern __shared__ char dsm[];
    uint32_t aHi = smem_u32(dsm);
    uint32_t aLo = aHi + 128 * SPB;
    uint32_t wHi = aLo + 128 * SPB;
    uint32_t wLo = wHi + N * SPB;

    const int tid = threadIdx.x, warp = tid >> 5, lane = tid & 31;
    const int base = blockIdx.x * 128;

    for (int i = tid; i < N * K / 2; i += 128) {
        int byte = i * 4;
        int row = byte / (K * 2), kb = byte - row * (K * 2);
        uint32_t off = (uint32_t)row * SPB + kb;
        sts32(wHi + off, ((const uint32_t*)Whi)[i]);
        sts32(wLo + off, ((const uint32_t*)Wlo)[i]);
    }
    constexpr int N4 = K / 4;
    for (int i = tid; i < 128 * N4; i += 128) {
        int row = i / N4, c4 = i - row * N4, col = c4 * 4;
        float4 v = make_float4(0.f, 0.f, 0.f, 0.f);
        if (base + row < N_NODES) v = ((const float4*)X)[(size_t)(base + row) * N4 + c4];
        uint32_t h01, l01, h23, l23;
        split2(v.x, v.y, h01, l01);
        split2(v.z, v.w, h23, l23);
        uint32_t off = (uint32_t)row * SPB + col * 2;
        sts32(aHi + off, h01); sts32(aHi + off + 4, h23);
        sts32(aLo + off, l01); sts32(aLo + off + 4, l23);
    }
    __syncthreads();

    float acc[2][NT][4];
#pragma unroll
    for (int t = 0; t < 2; t++)
#pragma unroll
        for (int n = 0; n < NT; n++)
#pragma unroll
            for (int j = 0; j < 4; j++) acc[t][n][j] = 0.f;

    const int arow = warp * 32 + (lane & 15);
    const int ahalf = lane >> 4;
    const int brow = lane & 7;
    const int bhalf = (lane >> 3) & 1;

#pragma unroll
    for (int s = 0; s < 3; s++) {
        uint32_t Ab = (s == 2) ? aLo : aHi;
        uint32_t Wb = (s == 1) ? wLo : wHi;
#pragma unroll
        for (int k16 = 0; k16 < K / 16; k16++) {
            uint32_t kbyte = (uint32_t)(k16 * 16) * 2;
            uint32_t af0[4], af1[4];
            ldsm4(af0, Ab + (uint32_t)arow * SPB + kbyte + ahalf * 16);
            ldsm4(af1, Ab + (uint32_t)(arow + 16) * SPB + kbyte + ahalf * 16);
#pragma unroll
            for (int n8 = 0; n8 < NT; n8++) {
                uint32_t bf[2];
                ldsm2(bf, Wb + (uint32_t)(n8 * 8 + brow) * SPB + kbyte + bhalf * 16);
                mma_bf16(acc[0][n8], af0, bf);
                mma_bf16(acc[1][n8], af1, bf);
            }
        }
    }
    const int r_in_warp = lane >> 2;
    const int cpair = (lane & 3) * 2;
#pragma unroll
    for (int t = 0; t < 2; t++) {
        int row0 = base + warp * 32 + t * 16 + r_in_warp;
        int row1 = row0 + 8;
#pragma unroll
        for (int n8 = 0; n8 < NT; n8++) {
            int col = n8 * 8 + cpair;
            if (row0 < N_NODES)
                *(uint32_t*)(Y + (size_t)row0 * N + col) = pack_bf16x2(acc[t][n8][0], acc[t][n8][1]);
            if (row1 < N_NODES)
                *(uint32_t*)(Y + (size_t)row1 * N + col) = pack_bf16x2(acc[t][n8][2], acc[t][n8][3]);
        }
    }
}

// ================= gather: 4 nodes/warp, 8 lanes/node, bf16 y rows =================
__global__ __launch_bounds__(256) void gather_kernel(const __nv_bfloat16* __restrict__ Y,
                                                     const int* __restrict__ rowptr,
                                                     const int* __restrict__ col,
                                                     const float* __restrict__ b1,
                                                     __nv_bfloat16* __restrict__ AGhi,
                                                     __nv_bfloat16* __restrict__ AGlo) {
    int w = (blockIdx.x * blockDim.x + threadIdx.x) >> 3;   // node id
    int lane = threadIdx.x & 7;                             // uint4 column (8 bf16)
    if (w >= N_NODES) return;
    const uint4* y4 = (const uint4*)Y;   // row = 8 uint4
    float bias[8];
    {
        float4 b0 = ((const float4*)b1)[lane * 2];
        float4 b1v = ((const float4*)b1)[lane * 2 + 1];
        bias[0] = b0.x; bias[1] = b0.y; bias[2] = b0.z; bias[3] = b0.w;
        bias[4] = b1v.x; bias[5] = b1v.y; bias[6] = b1v.z; bias[7] = b1v.w;
    }
    float acc[8], t0[8], t1[8], t2[8], t3[8];
    unpack8(y4[(size_t)w * 8 + lane], acc);
    int r0 = rowptr[w], r1 = rowptr[w + 1];
    int e = r0;
    for (; e + 3 < r1; e += 4) {
        uint4 a = y4[(size_t)col[e] * 8 + lane];
        uint4 b = y4[(size_t)col[e + 1] * 8 + lane];
        uint4 c = y4[(size_t)col[e + 2] * 8 + lane];
        uint4 d = y4[(size_t)col[e + 3] * 8 + lane];
        unpack8(a, t0); unpack8(b, t1); unpack8(c, t2); unpack8(d, t3);
#pragma unroll
        for (int j = 0; j < 8; j++) acc[j] += (t0[j] + t1[j]) + (t2[j] + t3[j]);
    }
    for (; e < r1; e++) {
        uint4 a = y4[(size_t)col[e] * 8 + lane];
        unpack8(a, t0);
#pragma unroll
        for (int j = 0; j < 8; j++) acc[j] += t0[j];
    }
#pragma unroll
    for (int j = 0; j < 8; j++) acc[j] = fmaxf(acc[j] + bias[j], 0.f);
    uint4 hv, lv;
    split2(acc[0], acc[1], hv.x, lv.x);
    split2(acc[2], acc[3], hv.y, lv.y);
    split2(acc[4], acc[5], hv.z, lv.z);
    split2(acc[6], acc[7], hv.w, lv.w);
    ((uint4*)AGhi)[(size_t)w * 8 + lane] = hv;
    ((uint4*)AGlo)[(size_t)w * 8 + lane] = lv;
}

// ================= fused MLP: AG(bf16) @ W2 -> BN+ReLU -> [@W1next -> Y(bf16) | bf16 out] =================
template <int NOUT, bool CHAIN>
__global__ __launch_bounds__(128) void fused_mlp(const __nv_bfloat16* __restrict__ AGhi,
                                                 const __nv_bfloat16* __restrict__ AGlo,
                                                 const __nv_bfloat16* __restrict__ W2hi,
                                                 const __nv_bfloat16* __restrict__ W2lo,
                                                 const float* __restrict__ b2,
                                                 const float* __restrict__ bng,
                                                 const float* __restrict__ bnb,
                                                 const float* __restrict__ bnm,
                                                 const float* __restrict__ bnv,
                                                 const __nv_bfloat16* __restrict__ W1hi,
                                                 const __nv_bfloat16* __restrict__ W1lo,
                                                 __nv_bfloat16* __restrict__ OUT) {
    constexpr int K = 64;
    constexpr int SP = K + 8, SPB = SP * 2;
    constexpr int NT = NOUT / 8;
    extern __shared__ char dsm[];
    uint32_t aHi = smem_u32(dsm);
    uint32_t aLo = aHi + 128 * SPB;
    uint32_t wHi = aLo + 128 * SPB;
    uint32_t wLo = wHi + NOUT * SPB;
    __shared__ float sScale[NOUT];
    __shared__ float sShift[NOUT];

    const int tid = threadIdx.x, warp = tid >> 5, lane = tid & 31;
    const int base = blockIdx.x * 128;

    if (tid < NOUT) {
        float s = bng[tid] * rsqrtf(bnv[tid] + BN_EPS);
        sScale[tid] = s;
        sShift[tid] = (b2[tid] - bnm[tid]) * s + bnb[tid];
    }
    for (int i = tid; i < NOUT * K / 2; i += 128) {
        int byte = i * 4;
        int row = byte >> 7, kb = byte & 127;
        uint32_t off = (uint32_t)row * SPB + kb;
        sts32(wHi + off, ((const uint32_t*)W2hi)[i]);
        sts32(wLo + off, ((const uint32_t*)W2lo)[i]);
    }
    for (int i = tid; i < 128 * 32; i += 128) {
        int row = i >> 5, w = i & 31;
        uint32_t h = 0, l = 0;
        if (base + row < N_NODES) {
            h = ((const uint32_t*)AGhi)[(size_t)(base + row) * 32 + w];
            l = ((const uint32_t*)AGlo)[(size_t)(base + row) * 32 + w];
        }
        uint32_t off = (uint32_t)row * SPB + w * 4;
        sts32(aHi + off, h);
        sts32(aLo + off, l);
    }
    __syncthreads();

    float acc[2][NT][4];
#pragma unroll
    for (int t = 0; t < 2; t++)
#pragma unroll
        for (int n = 0; n < NT; n++)
#pragma unroll
            for (int j = 0; j < 4; j++) acc[t][n][j] = 0.f;

    const int arow = warp * 32 + (lane & 15);
    const int ahalf = lane >> 4;
    const int brow = lane & 7;
    const int bhalf = (lane >> 3) & 1;

#pragma unroll
    for (int s = 0; s < 3; s++) {
        uint32_t Ab = (s == 2) ? aLo : aHi;
        uint32_t Wb = (s == 1) ? wLo : wHi;
#pragma unroll
        for (int k16 = 0; k16 < 4; k16++) {
            uint32_t kbyte = (uint32_t)(k16 * 32);
            uint32_t af0[4], af1[4];
            ldsm4(af0, Ab + (uint32_t)arow * SPB + kbyte + ahalf * 16);
            ldsm4(af1, Ab + (uint32_t)(arow + 16) * SPB + kbyte + ahalf * 16);
#pragma unroll
            for (int n8 = 0; n8 < NT; n8++) {
                uint32_t bf[2];
                ldsm2(bf, Wb + (uint32_t)(n8 * 8 + brow) * SPB + kbyte + bhalf * 16);
                mma_bf16(acc[0][n8], af0, bf);
                mma_bf16(acc[1][n8], af1, bf);
            }
        }
    }

    const int r_in_warp = lane >> 2;
    const int cpair = (lane & 3) * 2;
#pragma unroll
    for (int t = 0; t < 2; t++) {
#pragma unroll
        for (int n8 = 0; n8 < NT; n8++) {
            int c = n8 * 8 + cpair;
            acc[t][n8][0] = fmaxf(acc[t][n8][0] * sScale[c] + sShift[c], 0.f);
            acc[t][n8][1] = fmaxf(acc[t][n8][1] * sScale[c + 1] + sShift[c + 1], 0.f);
            acc[t][n8][2] = fmaxf(acc[t][n8][2] * sScale[c] + sShift[c], 0.f);
            acc[t][n8][3] = fmaxf(acc[t][n8][3] * sScale[c + 1] + sShift[c + 1], 0.f);
        }
    }

    if (!CHAIN) {
        // write final bf16 features [*,NOUT]
#pragma unroll
        for (int t = 0; t < 2; t++) {
            int row0 = base + warp * 32 + t * 16 + r_in_warp;
            int row1 = row0 + 8;
#pragma unroll
            for (int n8 = 0; n8 < NT; n8++) {
                int c = n8 * 8 + cpair;
                if (row0 < N_NODES)
                    *(uint32_t*)(OUT + (size_t)row0 * NOUT + c) = pack_bf16x2(acc[t][n8][0], acc[t][n8][1]);
                if (row1 < N_NODES)
                    *(uint32_t*)(OUT + (size_t)row1 * NOUT + c) = pack_bf16x2(acc[t][n8][2], acc[t][n8][3]);
            }
        }
        return;
    }

    // ---- chained next-layer GEMM1: y_next(bf16) = a @ W1next ----
    __syncthreads();
#pragma unroll
    for (int t = 0; t < 2; t++) {
        int rl0 = warp * 32 + t * 16 + r_in_warp;
        int rl1 = rl0 + 8;
#pragma unroll
        for (int n8 = 0; n8 < NT; n8++) {
            int cb = (n8 * 8 + cpair) * 2;
            uint32_t h, l;
            split2(acc[t][n8][0], acc[t][n8][1], h, l);
            sts32(aHi + (uint32_t)rl0 * SPB + cb, h);
            sts32(aLo + (uint32_t)rl0 * SPB + cb, l);
            split2(acc[t][n8][2], acc[t][n8][3], h, l);
            sts32(aHi + (uint32_t)rl1 * SPB + cb, h);
            sts32(aLo + (uint32_t)rl1 * SPB + cb, l);
        }
    }
    for (int i = tid; i < 64 * K / 2; i += 128) {
        int byte = i * 4;
        int row = byte >> 7, kb = byte & 127;
        uint32_t off = (uint32_t)row * SPB + kb;
        sts32(wHi + off, ((const uint32_t*)W1hi)[i]);
        sts32(wLo + off, ((const uint32_t*)W1lo)[i]);
    }
    __syncthreads();

    float acc2[2][8][4];
#pragma unroll
    for (int t = 0; t < 2; t++)
#pragma unroll
        for (int n = 0; n < 8; n++)
#pragma unroll
            for (int j = 0; j < 4; j++) acc2[t][n][j] = 0.f;

#pragma unroll
    for (int s = 0; s < 3; s++) {
        uint32_t Ab = (s == 2) ? aLo : aHi;
        uint32_t Wb = (s == 1) ? wLo : wHi;
#pragma unroll
        for (int k16 = 0; k16 < 4; k16++) {
            uint32_t kbyte = (uint32_t)(k16 * 32);
            uint32_t af0[4], af1[4];
            ldsm4(af0, Ab + (uint32_t)arow * SPB + kbyte + ahalf * 16);
            ldsm4(af1, Ab + (uint32_t)(arow + 16) * SPB + kbyte + ahalf * 16);
#pragma unroll
            for (int n8 = 0; n8 < 8; n8++) {
                uint32_t bf[2];
                ldsm2(bf, Wb + (uint32_t)(n8 * 8 + brow) * SPB + kbyte + bhalf * 16);
                mma_bf16(acc2[0][n8], af0, bf);
                mma_bf16(acc2[1][n8], af1, bf);
            }
        }
    }
#pragma unroll
    for (int t = 0; t < 2; t++) {
        int row0 = base + warp * 32 + t * 16 + r_in_warp;
        int row1 = row0 + 8;
#pragma unroll
        for (int n8 = 0; n8 < 8; n8++) {
            int c = n8 * 8 + cpair;
            if (row0 < N_NODES)
                *(uint32_t*)(OUT + (size_t)row0 * 64 + c) = pack_bf16x2(acc2[t][n8][0], acc2[t][n8][1]);
            if (row1 < N_NODES)
                *(uint32_t*)(OUT + (size_t)row1 * 64 + c) = pack_bf16x2(acc2[t][n8][2], acc2[t][n8][3]);
        }
    }
}

// ================= pool (reads bf16 features) =================
#define PB_NODES 64
__global__ void pool_kernel(const __nv_bfloat16* __restrict__ F, const int* __restrict__ batch,
                            float* __restrict__ sums, int* __restrict__ cnts) {
    __shared__ int sb[PB_NODES];
    const int start = blockIdx.x * PB_NODES;
    const int nn = min(PB_NODES, N_NODES - start);
    const int tid = threadIdx.x;   // 96
    if (tid < nn) sb[tid] = batch[start + tid];
    __syncthreads();
    if (tid == 0) {
        int cur = sb[0], c = 0;
        for (int n = 0; n < nn; n++) {
            int g = sb[n];
            if (g != cur) { atomicAdd(&cnts[cur], c); cur = g; c = 0; }
            c++;
        }
        atomicAdd(&cnts[cur], c);
    }
    int cur = sb[0];
    float acc = 0.f;
    for (int n = 0; n < nn; n++) {
        int g = sb[n];
        float v = __bfloat162float(F[(size_t)(start + n) * 96 + tid]);
        if (g != cur) { atomicAdd(&sums[cur * 96 + tid], acc); acc = 0.f; cur = g; }
        acc += v;
    }
    atomicAdd(&sums[cur * 96 + tid], acc);
}
__global__ void finalize_kernel(const float* __restrict__ sums, const int* __restrict__ cnts,
                                float* __restrict__ out) {
    int i = blockIdx.x * blockDim.x + threadIdx.x;
    if (i >= N_GRAPHS * 96) return;
    float c = fmaxf((float)cnts[i / 96], 1.f);
    out[i] = sums[i] / c;
}

// ================= launch =================
extern "C" void kernel_launch(void* const* d_in, const int* in_sizes, int n_in,
                              void* d_out, int out_size) {
    const float* x     = (const float*)d_in[0];
    const void*  ei    = d_in[1];
    const void*  batch = d_in[2];
    const float* P[24];
    for (int i = 0; i < 24; i++) P[i] = (const float*)d_in[3 + i];

    float *sums;
    __nv_bfloat16 *y, *aghi, *aglo, *whi, *wlo, *f;
    int *cnts, *b32, *flags;
    int *deg, *rowptr, *cursor, *colv;
    unsigned long long* sstate;
    cudaGetSymbolAddress((void**)&y,      g_y);
    cudaGetSymbolAddress((void**)&aghi,   g_aghi);
    cudaGetSymbolAddress((void**)&aglo,   g_aglo);
    cudaGetSymbolAddress((void**)&f,      g_f);
    cudaGetSymbolAddress((void**)&sums,   g_sums);
    cudaGetSymbolAddress((void**)&cnts,   g_cnts);
    cudaGetSymbolAddress((void**)&b32,    g_batch32);
    cudaGetSymbolAddress((void**)&flags,  g_flags);
    cudaGetSymbolAddress((void**)&deg,    g_deg);
    cudaGetSymbolAddress((void**)&rowptr, g_rowptr);
    cudaGetSymbolAddress((void**)&cursor, g_cursor);
    cudaGetSymbolAddress((void**)&colv,   g_col);
    cudaGetSymbolAddress((void**)&sstate, g_scanstate);
    cudaGetSymbolAddress((void**)&whi,    g_whi);
    cudaGetSymbolAddress((void**)&wlo,    g_wlo);

    const int SM_L0  = (256 + 128) * (136 * 2);   // 104448
    const int SM_F64 = (256 + 128) * (72 * 2);    // 55296
    const int SM_F96 = (256 + 192) * (72 * 2);    // 64512
    cudaFuncSetAttribute((const void*)hgemm_l0, cudaFuncAttributeMaxDynamicSharedMemorySize, SM_L0);
    cudaFuncSetAttribute((const void*)fused_mlp<64, true>,  cudaFuncAttributeMaxDynamicSharedMemorySize, SM_F64);
    cudaFuncSetAttribute((const void*)fused_mlp<96, false>, cudaFuncAttributeMaxDynamicSharedMemorySize, SM_F96);

    const int NB = (N_NODES + 127) / 128;          // 782
    const int GB = (N_NODES * 8 + 255) / 256;      // 3125 (8 lanes per node)

    cudaStream_t s2;
    cudaStreamCreateWithFlags(&s2, cudaStreamNonBlocking);
    cudaEvent_t evFork, evJoin, evFlags;
    cudaEventCreateWithFlags(&evFork, cudaEventDisableTiming);
    cudaEventCreateWithFlags(&evJoin, cudaEventDisableTiming);
    cudaEventCreateWithFlags(&evFlags, cudaEventDisableTiming);

    cudaEventRecord(evFork, 0);
    cudaStreamWaitEvent(s2, evFork, 0);

    // --- branch A (stream 0): CSR build ---
    prep_graph_kernel<<<NB_SCAN + 2, 256>>>(ei, batch, flags, deg, sstate);
    cudaEventRecord(evFlags, 0);
    hist_kernel<<<EB4, 256>>>(ei, flags, deg);
    scan_onepass_kernel<<<NB_SCAN, SCAN_BS>>>(deg, rowptr, cursor, sstate);
    fill_kernel<<<EB4, 256>>>(ei, flags, cursor, colv);

    // --- branch B (s2): weights + layer-0 GEMM + batch convert + pool zero ---
    const int O_W10 = 0, O_W20 = 8192, O_W11 = 12288, O_W21 = 16384, O_W12 = 20480, O_W22 = 24576;
    wsplit_kernel<<<WB, 256, 0, s2>>>(P[0], P[2], P[8], P[10], P[16], P[18], whi, wlo);
    hgemm_l0<<<NB, 128, SM_L0, s2>>>(x, whi + O_W10, wlo + O_W10, y);
    cudaStreamWaitEvent(s2, evFlags, 0);
    side_kernel<<<NBB + 1, 256, 0, s2>>>(batch, flags, b32, sums, cnts);
    cudaEventRecord(evJoin, s2);

    cudaStreamWaitEvent(0, evJoin, 0);

    gather_kernel<<<GB, 256>>>(y, rowptr, colv, P[1], aghi, aglo);
    fused_mlp<64, true><<<NB, 128, SM_F64>>>(aghi, aglo, whi + O_W20, wlo + O_W20,
                                             P[3], P[4], P[5], P[6], P[7],
                                             whi + O_W11, wlo + O_W11, y);
    gather_kernel<<<GB, 256>>>(y, rowptr, colv, P[9], aghi, aglo);
    fused_mlp<64, true><<<NB, 128, SM_F64>>>(aghi, aglo, whi + O_W21, wlo + O_W21,
                                             P[11], P[12], P[13], P[14], P[15],
                                             whi + O_W12, wlo + O_W12, y);
    gather_kernel<<<GB, 256>>>(y, rowptr, colv, P[17], aghi, aglo);
    fused_mlp<96, false><<<NB, 128, SM_F96>>>(aghi, aglo, whi + O_W22, wlo + O_W22,
                                              P[19], P[20], P[21], P[22], P[23],
                                              nullptr, nullptr, f);

    pool_kernel<<<(N_NODES + PB_NODES - 1) / PB_NODES, 96>>>(f, b32, sums, cnts);
    finalize_kernel<<<(N_GRAPHS * 96 + 255) / 256, 256>>>(sums, cnts, (float*)d_out);

    cudaEventDestroy(evFork);
    cudaEventDestroy(evJoin);
    cudaEventDestroy(evFlags);
    cudaStreamDestroy(s2);
}